// round 1
// baseline (speedup 1.0000x reference)
#include <cuda_runtime.h>

#define D  128
#define TM 64
#define KB 16

// Scratch: zv [2*NC*D] | zc [2*NV*D] | mv [NV*D] | mc [NC*D]
// = 102.4M + 25.6M + 12.8M + 51.2M = 192M floats (768 MB)
__device__ float g_scratch[192000000];

// Fused 2-layer MLP: out = relu(relu([x1|x2] @ W1 + b1) @ W2 + b2)
// x1,x2: [n, D] (x2 may be null -> K1 = D, else K1 = 2D with W1 = [2D, D])
// W row-major [K, 128]. Block: 64 rows x 128 cols, 256 threads, 8x4 microtile.
__global__ __launch_bounds__(256)
void fused_mlp2_kernel(const float* __restrict__ x1,
                       const float* __restrict__ x2,
                       int n,
                       const float* __restrict__ W1,
                       const float* __restrict__ b1,
                       const float* __restrict__ W2,
                       const float* __restrict__ b2,
                       float* __restrict__ out)
{
    __shared__ float xs[KB][TM + 4];   // k-major x tile
    __shared__ float ws[KB][D];        // weight chunk
    __shared__ float hs[D][TM + 4];    // hidden activations, k-major

    const int tid = threadIdx.x;
    const int tx  = tid & 31;          // col group: cols tx*4 .. tx*4+3
    const int ty  = tid >> 5;          // row group: rows ty*8 .. ty*8+7
    const int row0 = blockIdx.x * TM;

    float acc[8][4];
    #pragma unroll
    for (int i = 0; i < 8; ++i)
        #pragma unroll
        for (int j = 0; j < 4; ++j) acc[i][j] = 0.0f;

    // x-tile loader mapping: thread -> (row lr, 4 k's at lk)
    const int lr = tid >> 2;
    const int lk = (tid & 3) * 4;
    // w-tile loader mapping: thread -> (k row wk, 8 cols at wc)
    const int wk = tid >> 4;
    const int wc = (tid & 15) * 8;

    const int gr = row0 + lr;
    const int nsrc = (x2 != nullptr) ? 2 : 1;

    // ---------------- Layer 1 ----------------
    for (int s = 0; s < nsrc; ++s) {
        const float* xp = (s == 0) ? x1 : x2;
        const float* wp = W1 + (size_t)s * D * D;   // rows s*128 .. s*128+127
        for (int k0 = 0; k0 < D; k0 += KB) {
            float4 xv = make_float4(0.f, 0.f, 0.f, 0.f);
            if (gr < n)
                xv = *(const float4*)(xp + (size_t)gr * D + k0 + lk);
            const float* wrow = wp + (size_t)(k0 + wk) * D + wc;
            float4 w0 = *(const float4*)(wrow);
            float4 w1 = *(const float4*)(wrow + 4);

            __syncthreads();  // previous chunk fully consumed
            xs[lk + 0][lr] = xv.x;
            xs[lk + 1][lr] = xv.y;
            xs[lk + 2][lr] = xv.z;
            xs[lk + 3][lr] = xv.w;
            *(float4*)&ws[wk][wc]     = w0;
            *(float4*)&ws[wk][wc + 4] = w1;
            __syncthreads();

            #pragma unroll
            for (int k = 0; k < KB; ++k) {
                float4 a0 = *(const float4*)&xs[k][ty * 8];
                float4 a1 = *(const float4*)&xs[k][ty * 8 + 4];
                float4 wv = *(const float4*)&ws[k][tx * 4];
                float a[8] = {a0.x, a0.y, a0.z, a0.w, a1.x, a1.y, a1.z, a1.w};
                float w[4] = {wv.x, wv.y, wv.z, wv.w};
                #pragma unroll
                for (int i = 0; i < 8; ++i)
                    #pragma unroll
                    for (int j = 0; j < 4; ++j)
                        acc[i][j] = fmaf(a[i], w[j], acc[i][j]);
            }
        }
    }

    // bias + relu -> hs (k-major), reset acc
    {
        float4 bb = *(const float4*)(b1 + tx * 4);
        float bj[4] = {bb.x, bb.y, bb.z, bb.w};
        __syncthreads();  // all reads of xs/ws done
        #pragma unroll
        for (int i = 0; i < 8; ++i)
            #pragma unroll
            for (int j = 0; j < 4; ++j) {
                hs[tx * 4 + j][ty * 8 + i] = fmaxf(acc[i][j] + bj[j], 0.0f);
                acc[i][j] = 0.0f;
            }
    }

    // ---------------- Layer 2 ----------------
    for (int k0 = 0; k0 < D; k0 += KB) {
        const float* wrow = W2 + (size_t)(k0 + wk) * D + wc;
        float4 w0 = *(const float4*)(wrow);
        float4 w1 = *(const float4*)(wrow + 4);
        __syncthreads();  // hs written / previous ws consumed
        *(float4*)&ws[wk][wc]     = w0;
        *(float4*)&ws[wk][wc + 4] = w1;
        __syncthreads();

        #pragma unroll
        for (int k = 0; k < KB; ++k) {
            float4 a0 = *(const float4*)&hs[k0 + k][ty * 8];
            float4 a1 = *(const float4*)&hs[k0 + k][ty * 8 + 4];
            float4 wv = *(const float4*)&ws[k][tx * 4];
            float a[8] = {a0.x, a0.y, a0.z, a0.w, a1.x, a1.y, a1.z, a1.w};
            float w[4] = {wv.x, wv.y, wv.z, wv.w};
            #pragma unroll
            for (int i = 0; i < 8; ++i)
                #pragma unroll
                for (int j = 0; j < 4; ++j)
                    acc[i][j] = fmaf(a[i], w[j], acc[i][j]);
        }
    }

    // bias + relu -> global out
    {
        float4 bb = *(const float4*)(b2 + tx * 4);
        #pragma unroll
        for (int i = 0; i < 8; ++i) {
            int r = row0 + ty * 8 + i;
            if (r < n) {
                float4 o;
                o.x = fmaxf(acc[i][0] + bb.x, 0.0f);
                o.y = fmaxf(acc[i][1] + bb.y, 0.0f);
                o.z = fmaxf(acc[i][2] + bb.z, 0.0f);
                o.w = fmaxf(acc[i][3] + bb.w, 0.0f);
                *(float4*)(out + (size_t)r * D + tx * 4) = o;
            }
        }
    }
}

// One warp per edge: gather z[col[e]] (512B coalesced) and red.add into m[row[e]].
__global__ __launch_bounds__(256)
void scatter_add_kernel(const float* __restrict__ z,
                        const int* __restrict__ col,
                        const int* __restrict__ row,
                        float* __restrict__ m,
                        int nedges)
{
    long long idx = (long long)blockIdx.x * blockDim.x + threadIdx.x;
    int e  = (int)(idx >> 5);
    int ch = (int)(idx & 31);
    if (e < nedges) {
        int c = __ldg(col + e);
        int r = __ldg(row + e);
        float4 v = ((const float4*)(z + (size_t)c * D))[ch];
        float* dst = m + (size_t)r * D + ch * 4;
        asm volatile("red.global.add.v4.f32 [%0], {%1, %2, %3, %4};"
                     :: "l"(__cvta_generic_to_global(dst)),
                        "f"(v.x), "f"(v.y), "f"(v.z), "f"(v.w)
                     : "memory");
    }
}

extern "C" void kernel_launch(void* const* d_in, const int* in_sizes, int n_in,
                              void* d_out, int out_size)
{
    const float* hv    = (const float*)d_in[0];
    const float* hc    = (const float*)d_in[1];
    const int*   row_v = (const int*)d_in[2];
    const int*   col_v = (const int*)d_in[3];
    const int*   row_c = (const int*)d_in[4];
    const int*   col_c = (const int*)d_in[5];
    const float* mw1   = (const float*)d_in[6];   // [4][128][128]
    const float* mb1   = (const float*)d_in[7];   // [4][128]
    const float* mw2   = (const float*)d_in[8];   // [4][128][128]
    const float* mb2   = (const float*)d_in[9];   // [4][128]
    const float* uw1   = (const float*)d_in[10];  // [2][256][128]
    const float* ub1   = (const float*)d_in[11];  // [2][128]
    const float* uw2   = (const float*)d_in[12];  // [2][128][128]
    const float* ub2   = (const float*)d_in[13];  // [2][128]

    const int NV = in_sizes[0] / D;   // 100000
    const int NC = in_sizes[1] / D;   // 400000
    const int E  = in_sizes[2];       // 1600000

    float* scratch;
    cudaGetSymbolAddress((void**)&scratch, g_scratch);
    float* zv = scratch;                          // [2*NC, D]
    float* zc = zv + (size_t)2 * NC * D;          // [2*NV, D]
    float* mv = zc + (size_t)2 * NV * D;          // [NV, D]
    float* mc = mv + (size_t)NV * D;              // [NC, D]

    float* hv_new = (float*)d_out;
    float* hc_new = hv_new + (size_t)NV * D;

    // zero the message accumulators
    cudaMemsetAsync(mv, 0, (size_t)(NV + NC) * D * sizeof(float), 0);

    dim3 blk(256);
    int gc = (NC + TM - 1) / TM;
    int gv = (NV + TM - 1) / TM;

    // message MLPs
    fused_mlp2_kernel<<<gc, blk>>>(hc, nullptr, NC,
        mw1 + 0 * D * D, mb1 + 0 * D, mw2 + 0 * D * D, mb2 + 0 * D, zv);
    fused_mlp2_kernel<<<gc, blk>>>(hc, nullptr, NC,
        mw1 + 1 * D * D, mb1 + 1 * D, mw2 + 1 * D * D, mb2 + 1 * D, zv + (size_t)NC * D);
    fused_mlp2_kernel<<<gv, blk>>>(hv, nullptr, NV,
        mw1 + 2 * D * D, mb1 + 2 * D, mw2 + 2 * D * D, mb2 + 2 * D, zc);
    fused_mlp2_kernel<<<gv, blk>>>(hv, nullptr, NV,
        mw1 + 3 * D * D, mb1 + 3 * D, mw2 + 3 * D * D, mb2 + 3 * D, zc + (size_t)NV * D);

    // edge scatter-adds (one warp per edge)
    long long tscat = (long long)E * 32;
    int gs = (int)((tscat + 255) / 256);
    scatter_add_kernel<<<gs, blk>>>(zv, col_v, row_v, mv, E);
    scatter_add_kernel<<<gs, blk>>>(zc, col_c, row_c, mc, E);

    // update MLPs (concat(h, m) via split-K)
    fused_mlp2_kernel<<<gv, blk>>>(hv, mv, NV,
        uw1 + 0 * 2 * D * D, ub1 + 0 * D, uw2 + 0 * D * D, ub2 + 0 * D, hv_new);
    fused_mlp2_kernel<<<gc, blk>>>(hc, mc, NC,
        uw1 + 1 * 2 * D * D, ub1 + 1 * D, uw2 + 1 * D * D, ub2 + 1 * D, hc_new);
}

// round 2
// speedup vs baseline: 1.0471x; 1.0471x over previous
#include <cuda_runtime.h>

#define D   128
#define TMR 128
#define KB  16
#define XSTR (TMR + 4)   // 132: row stride for k-major tiles

// Scratch: zv [2*NC*D] | zc [2*NV*D] | mv [NV*D] | mc [NC*D]
__device__ float g_scratch[192000000];

// ---------- packed f32x2 helpers ----------
__device__ __forceinline__ unsigned long long pack2(float x, float y) {
    unsigned long long r;
    asm("mov.b64 %0, {%1, %2};" : "=l"(r) : "f"(x), "f"(y));
    return r;
}
__device__ __forceinline__ void unpack2(unsigned long long v, float& x, float& y) {
    asm("mov.b64 {%0, %1}, %2;" : "=f"(x), "=f"(y) : "l"(v));
}
__device__ __forceinline__ unsigned long long fma2(unsigned long long a,
                                                   unsigned long long b,
                                                   unsigned long long c) {
    unsigned long long d;
    asm("fma.rn.f32x2 %0, %1, %2, %3;" : "=l"(d) : "l"(a), "l"(b), "l"(c));
    return d;
}

extern __shared__ float smem_dyn[];

// Fused 2-layer MLP: out = relu(relu([x1|x2] @ W1 + b1) @ W2 + b2)
// 128x128 block tile, 256 threads, 8x8 microtile, packed f32x2 FMA.
__global__ __launch_bounds__(256, 2)
void fused_mlp2_kernel(const float* __restrict__ x1,
                       const float* __restrict__ x2,
                       int n,
                       const float* __restrict__ W1,
                       const float* __restrict__ b1,
                       const float* __restrict__ W2,
                       const float* __restrict__ b2,
                       float* __restrict__ out)
{
    float* xs = smem_dyn;                  // [KB][XSTR]   k-major x tile
    float* ws = xs + KB * XSTR;            // [KB][D]      weight chunk
    float* hs = ws + KB * D;               // [D][XSTR]    hidden acts, k-major

    const int tid = threadIdx.x;
    const int tx  = tid & 15;              // col group: cols tx*8 .. +7
    const int ty  = tid >> 4;              // row group: rows ty*8 .. +7
    const int row0 = blockIdx.x * TMR;

    unsigned long long acc[8][4];          // [row][col-pair]
    #pragma unroll
    for (int i = 0; i < 8; ++i)
        #pragma unroll
        for (int j = 0; j < 4; ++j) acc[i][j] = 0ull;

    // x loader: thread -> (row lr, 8 k's at lk)
    const int lr = tid >> 1;
    const int lk = (tid & 1) * 8;
    // w loader: thread -> (k row wk, 8 cols at wc)
    const int wk = tid >> 4;
    const int wc = (tid & 15) * 8;

    const int gr = row0 + lr;
    const int nsrc = (x2 != nullptr) ? 2 : 1;

    // ---------------- Layer 1 ----------------
    for (int s = 0; s < nsrc; ++s) {
        const float* xp = (s == 0) ? x1 : x2;
        const float* wp = W1 + (size_t)s * D * D;
        for (int k0 = 0; k0 < D; k0 += KB) {
            float4 v0 = make_float4(0.f, 0.f, 0.f, 0.f);
            float4 v1 = make_float4(0.f, 0.f, 0.f, 0.f);
            if (gr < n) {
                v0 = *(const float4*)(xp + (size_t)gr * D + k0 + lk);
                v1 = *(const float4*)(xp + (size_t)gr * D + k0 + lk + 4);
            }
            const float* wrow = wp + (size_t)(k0 + wk) * D + wc;
            float4 w0 = *(const float4*)(wrow);
            float4 w1 = *(const float4*)(wrow + 4);

            __syncthreads();   // previous chunk fully consumed
            xs[(lk + 0) * XSTR + lr] = v0.x;
            xs[(lk + 1) * XSTR + lr] = v0.y;
            xs[(lk + 2) * XSTR + lr] = v0.z;
            xs[(lk + 3) * XSTR + lr] = v0.w;
            xs[(lk + 4) * XSTR + lr] = v1.x;
            xs[(lk + 5) * XSTR + lr] = v1.y;
            xs[(lk + 6) * XSTR + lr] = v1.z;
            xs[(lk + 7) * XSTR + lr] = v1.w;
            *(float4*)&ws[wk * D + wc]     = w0;
            *(float4*)&ws[wk * D + wc + 4] = w1;
            __syncthreads();

            #pragma unroll
            for (int k = 0; k < KB; ++k) {
                float4 a0 = *(const float4*)&xs[k * XSTR + ty * 8];
                float4 a1 = *(const float4*)&xs[k * XSTR + ty * 8 + 4];
                float4 u0 = *(const float4*)&ws[k * D + tx * 8];
                float4 u1 = *(const float4*)&ws[k * D + tx * 8 + 4];
                unsigned long long wpk[4] = {
                    pack2(u0.x, u0.y), pack2(u0.z, u0.w),
                    pack2(u1.x, u1.y), pack2(u1.z, u1.w)
                };
                float a[8] = {a0.x, a0.y, a0.z, a0.w, a1.x, a1.y, a1.z, a1.w};
                #pragma unroll
                for (int i = 0; i < 8; ++i) {
                    unsigned long long ad = pack2(a[i], a[i]);
                    #pragma unroll
                    for (int j = 0; j < 4; ++j)
                        acc[i][j] = fma2(ad, wpk[j], acc[i][j]);
                }
            }
        }
    }

    // bias + relu -> hs (k-major), reset acc
    {
        float4 bb0 = *(const float4*)(b1 + tx * 8);
        float4 bb1 = *(const float4*)(b1 + tx * 8 + 4);
        float bj[8] = {bb0.x, bb0.y, bb0.z, bb0.w, bb1.x, bb1.y, bb1.z, bb1.w};
        #pragma unroll
        for (int i = 0; i < 8; ++i)
            #pragma unroll
            for (int j = 0; j < 4; ++j) {
                float c0, c1;
                unpack2(acc[i][j], c0, c1);
                hs[(tx * 8 + 2 * j + 0) * XSTR + ty * 8 + i] = fmaxf(c0 + bj[2 * j + 0], 0.0f);
                hs[(tx * 8 + 2 * j + 1) * XSTR + ty * 8 + i] = fmaxf(c1 + bj[2 * j + 1], 0.0f);
                acc[i][j] = 0ull;
            }
    }

    // ---------------- Layer 2 ----------------
    for (int k0 = 0; k0 < D; k0 += KB) {
        const float* wrow = W2 + (size_t)(k0 + wk) * D + wc;
        float4 w0 = *(const float4*)(wrow);
        float4 w1 = *(const float4*)(wrow + 4);
        __syncthreads();   // hs writes done / previous ws consumed
        *(float4*)&ws[wk * D + wc]     = w0;
        *(float4*)&ws[wk * D + wc + 4] = w1;
        __syncthreads();

        #pragma unroll
        for (int k = 0; k < KB; ++k) {
            float4 a0 = *(const float4*)&hs[(k0 + k) * XSTR + ty * 8];
            float4 a1 = *(const float4*)&hs[(k0 + k) * XSTR + ty * 8 + 4];
            float4 u0 = *(const float4*)&ws[k * D + tx * 8];
            float4 u1 = *(const float4*)&ws[k * D + tx * 8 + 4];
            unsigned long long wpk[4] = {
                pack2(u0.x, u0.y), pack2(u0.z, u0.w),
                pack2(u1.x, u1.y), pack2(u1.z, u1.w)
            };
            float a[8] = {a0.x, a0.y, a0.z, a0.w, a1.x, a1.y, a1.z, a1.w};
            #pragma unroll
            for (int i = 0; i < 8; ++i) {
                unsigned long long ad = pack2(a[i], a[i]);
                #pragma unroll
                for (int j = 0; j < 4; ++j)
                    acc[i][j] = fma2(ad, wpk[j], acc[i][j]);
            }
        }
    }

    // bias + relu -> global out
    {
        float4 bb0 = *(const float4*)(b2 + tx * 8);
        float4 bb1 = *(const float4*)(b2 + tx * 8 + 4);
        float bj[8] = {bb0.x, bb0.y, bb0.z, bb0.w, bb1.x, bb1.y, bb1.z, bb1.w};
        #pragma unroll
        for (int i = 0; i < 8; ++i) {
            int r = row0 + ty * 8 + i;
            if (r < n) {
                float o[8];
                #pragma unroll
                for (int j = 0; j < 4; ++j) {
                    float c0, c1;
                    unpack2(acc[i][j], c0, c1);
                    o[2 * j + 0] = fmaxf(c0 + bj[2 * j + 0], 0.0f);
                    o[2 * j + 1] = fmaxf(c1 + bj[2 * j + 1], 0.0f);
                }
                *(float4*)(out + (size_t)r * D + tx * 8)     = make_float4(o[0], o[1], o[2], o[3]);
                *(float4*)(out + (size_t)r * D + tx * 8 + 4) = make_float4(o[4], o[5], o[6], o[7]);
            }
        }
    }
}

// One warp per edge: gather z[col[e]] (512B coalesced) and red.add into m[row[e]].
__global__ __launch_bounds__(256)
void scatter_add_kernel(const float* __restrict__ z,
                        const int* __restrict__ col,
                        const int* __restrict__ row,
                        float* __restrict__ m,
                        int nedges)
{
    long long idx = (long long)blockIdx.x * blockDim.x + threadIdx.x;
    int e  = (int)(idx >> 5);
    int ch = (int)(idx & 31);
    if (e < nedges) {
        int c = __ldg(col + e);
        int r = __ldg(row + e);
        float4 v = ((const float4*)(z + (size_t)c * D))[ch];
        float* dst = m + (size_t)r * D + ch * 4;
        asm volatile("red.global.add.v4.f32 [%0], {%1, %2, %3, %4};"
                     :: "l"(__cvta_generic_to_global(dst)),
                        "f"(v.x), "f"(v.y), "f"(v.z), "f"(v.w)
                     : "memory");
    }
}

extern "C" void kernel_launch(void* const* d_in, const int* in_sizes, int n_in,
                              void* d_out, int out_size)
{
    const float* hv    = (const float*)d_in[0];
    const float* hc    = (const float*)d_in[1];
    const int*   row_v = (const int*)d_in[2];
    const int*   col_v = (const int*)d_in[3];
    const int*   row_c = (const int*)d_in[4];
    const int*   col_c = (const int*)d_in[5];
    const float* mw1   = (const float*)d_in[6];
    const float* mb1   = (const float*)d_in[7];
    const float* mw2   = (const float*)d_in[8];
    const float* mb2   = (const float*)d_in[9];
    const float* uw1   = (const float*)d_in[10];
    const float* ub1   = (const float*)d_in[11];
    const float* uw2   = (const float*)d_in[12];
    const float* ub2   = (const float*)d_in[13];

    const int NV = in_sizes[0] / D;   // 100000
    const int NC = in_sizes[1] / D;   // 400000
    const int E  = in_sizes[2];       // 1600000

    float* scratch;
    cudaGetSymbolAddress((void**)&scratch, g_scratch);
    float* zv = scratch;                          // [2*NC, D]
    float* zc = zv + (size_t)2 * NC * D;          // [2*NV, D]
    float* mv = zc + (size_t)2 * NV * D;          // [NV, D]
    float* mc = mv + (size_t)NV * D;              // [NC, D]

    float* hv_new = (float*)d_out;
    float* hc_new = hv_new + (size_t)NV * D;

    const int smem_bytes = (KB * XSTR + KB * D + D * XSTR) * sizeof(float);
    cudaFuncSetAttribute(fused_mlp2_kernel,
                         cudaFuncAttributeMaxDynamicSharedMemorySize, smem_bytes);

    cudaMemsetAsync(mv, 0, (size_t)(NV + NC) * D * sizeof(float), 0);

    dim3 blk(256);
    int gc = (NC + TMR - 1) / TMR;
    int gv = (NV + TMR - 1) / TMR;

    // message MLPs
    fused_mlp2_kernel<<<gc, blk, smem_bytes>>>(hc, nullptr, NC,
        mw1 + 0 * D * D, mb1 + 0 * D, mw2 + 0 * D * D, mb2 + 0 * D, zv);
    fused_mlp2_kernel<<<gc, blk, smem_bytes>>>(hc, nullptr, NC,
        mw1 + 1 * D * D, mb1 + 1 * D, mw2 + 1 * D * D, mb2 + 1 * D, zv + (size_t)NC * D);
    fused_mlp2_kernel<<<gv, blk, smem_bytes>>>(hv, nullptr, NV,
        mw1 + 2 * D * D, mb1 + 2 * D, mw2 + 2 * D * D, mb2 + 2 * D, zc);
    fused_mlp2_kernel<<<gv, blk, smem_bytes>>>(hv, nullptr, NV,
        mw1 + 3 * D * D, mb1 + 3 * D, mw2 + 3 * D * D, mb2 + 3 * D, zc + (size_t)NV * D);

    // edge scatter-adds (one warp per edge)
    long long tscat = (long long)E * 32;
    int gs = (int)((tscat + 255) / 256);
    scatter_add_kernel<<<gs, blk>>>(zv, col_v, row_v, mv, E);
    scatter_add_kernel<<<gs, blk>>>(zc, col_c, row_c, mc, E);

    // update MLPs (concat(h, m) via split-K)
    fused_mlp2_kernel<<<gv, blk, smem_bytes>>>(hv, mv, NV,
        uw1 + 0 * 2 * D * D, ub1 + 0 * D, uw2 + 0 * D * D, ub2 + 0 * D, hv_new);
    fused_mlp2_kernel<<<gc, blk, smem_bytes>>>(hc, mc, NC,
        uw1 + 1 * 2 * D * D, ub1 + 1 * D, uw2 + 1 * D * D, ub2 + 1 * D, hc_new);
}

// round 4
// speedup vs baseline: 1.7043x; 1.6276x over previous
#include <cuda_runtime.h>
#include <cuda_bf16.h>
#include <cstdint>

#define D 128

// Scratch floats: zv [2*NC*D] | zc [2*NV*D] | mv [NV*D] | mc [NC*D] = 192M f
// then bf16 region: split inputs/messages + transposed split weights
__device__ float g_scratch[320400000];

// ---------------- helpers ----------------
__device__ __forceinline__ uint32_t smem_u32(const void* p) {
    uint32_t a;
    asm("{ .reg .u64 t; cvta.to.shared.u64 t, %1; cvt.u32.u64 %0, t; }"
        : "=r"(a) : "l"(p));
    return a;
}

__device__ __forceinline__ void mma16816(float c[4],
                                         uint32_t a0, uint32_t a1, uint32_t a2, uint32_t a3,
                                         uint32_t b0, uint32_t b1) {
    asm volatile(
        "mma.sync.aligned.m16n8k16.row.col.f32.bf16.bf16.f32 "
        "{%0,%1,%2,%3}, {%4,%5,%6,%7}, {%8,%9}, {%0,%1,%2,%3};"
        : "+f"(c[0]), "+f"(c[1]), "+f"(c[2]), "+f"(c[3])
        : "r"(a0), "r"(a1), "r"(a2), "r"(a3), "r"(b0), "r"(b1));
}

__device__ __forceinline__ void ldmx4(uint32_t& r0, uint32_t& r1, uint32_t& r2, uint32_t& r3,
                                      uint32_t addr) {
    asm volatile("ldmatrix.sync.aligned.m8n8.x4.shared.b16 {%0,%1,%2,%3}, [%4];"
                 : "=r"(r0), "=r"(r1), "=r"(r2), "=r"(r3) : "r"(addr));
}

// smem layout (bytes). Row stride 136 bf16 = 272B (conflict-free ldmatrix).
#define XSTRD 136
#define SM_XHI 0
#define SM_XLO 34816
#define SM_WHI 69632
#define SM_WLO 104448
#define SM_B1S 139264
#define SM_B2S 139776
#define SMEM_BYTES 140800

extern __shared__ char smem_raw[];

// load 128x128 bf16 tile (hi+lo) from global rows [row0, row0+128) into smem
__device__ __forceinline__ void load_x(const __nv_bfloat16* gh, const __nv_bfloat16* gl,
                                       int row0, int n, char* sb, int tid) {
    __nv_bfloat16* xh = (__nv_bfloat16*)(sb + SM_XHI);
    __nv_bfloat16* xl = (__nv_bfloat16*)(sb + SM_XLO);
    #pragma unroll
    for (int f = tid; f < 2048; f += 256) {
        int row = f >> 4, q = f & 15;
        int gr = row0 + row;
        uint4 vh = make_uint4(0, 0, 0, 0), vl = make_uint4(0, 0, 0, 0);
        if (gr < n) {
            vh = *(const uint4*)(gh + (size_t)gr * D + q * 8);
            vl = *(const uint4*)(gl + (size_t)gr * D + q * 8);
        }
        *(uint4*)(xh + row * XSTRD + q * 8) = vh;
        *(uint4*)(xl + row * XSTRD + q * 8) = vl;
    }
}

// load W^T [128][K] chunk cols [k0, k0+128) (hi+lo) into smem
__device__ __forceinline__ void load_w(const __nv_bfloat16* gh, const __nv_bfloat16* gl,
                                       int K, int k0, char* sb, int tid) {
    __nv_bfloat16* wh = (__nv_bfloat16*)(sb + SM_WHI);
    __nv_bfloat16* wl = (__nv_bfloat16*)(sb + SM_WLO);
    #pragma unroll
    for (int f = tid; f < 2048; f += 256) {
        int row = f >> 4, q = f & 15;
        uint4 vh = *(const uint4*)(gh + (size_t)row * K + k0 + q * 8);
        uint4 vl = *(const uint4*)(gl + (size_t)row * K + k0 + q * 8);
        *(uint4*)(wh + row * XSTRD + q * 8) = vh;
        *(uint4*)(wl + row * XSTRD + q * 8) = vl;
    }
}

// 3-term bf16-split accumulate: acc += X @ W^T over 128 k's in smem
__device__ __forceinline__ void compute_terms(float acc[4][4][4], char* sb,
                                              int wm, int wn, int lane) {
    const uint32_t xhi = smem_u32(sb + SM_XHI);
    const uint32_t xlo = smem_u32(sb + SM_XLO);
    const uint32_t whi = smem_u32(sb + SM_WHI);
    const uint32_t wlo = smem_u32(sb + SM_WLO);
    const int g  = lane >> 2;
    const int tg = lane & 3;
    // ldmatrix per-lane offset: row = lane%16, col-block = (lane/16)*8
    const uint32_t aoff = (uint32_t)((lane & 15) * XSTRD + (lane >> 4) * 8) * 2;

    #pragma unroll
    for (int t = 0; t < 3; ++t) {
        const uint32_t abase = (t == 2) ? xlo : xhi;
        const uint32_t bbase = (t == 1) ? wlo : whi;
        #pragma unroll
        for (int ks = 0; ks < 8; ++ks) {
            const int k0 = ks * 16;
            uint32_t a[4][4];
            #pragma unroll
            for (int mt = 0; mt < 4; ++mt) {
                uint32_t addr = abase + (uint32_t)((wm * 64 + mt * 16) * XSTRD + k0) * 2 + aoff;
                ldmx4(a[mt][0], a[mt][1], a[mt][2], a[mt][3], addr);
            }
            uint32_t b[4][2];
            #pragma unroll
            for (int nt = 0; nt < 4; ++nt) {
                int n = wn * 32 + nt * 8 + g;
                const char* base = (const char*)0;
                uint32_t rowoff = (uint32_t)(n * XSTRD) * 2;
                uint32_t p0 = bbase + rowoff + (uint32_t)(k0 + tg * 2) * 2;
                uint32_t p1 = p0 + 16;
                asm volatile("ld.shared.b32 %0, [%1];" : "=r"(b[nt][0]) : "r"(p0));
                asm volatile("ld.shared.b32 %0, [%1];" : "=r"(b[nt][1]) : "r"(p1));
                (void)base;
            }
            #pragma unroll
            for (int mt = 0; mt < 4; ++mt)
                #pragma unroll
                for (int nt = 0; nt < 4; ++nt)
                    mma16816(acc[mt][nt], a[mt][0], a[mt][1], a[mt][2], a[mt][3],
                             b[nt][0], b[nt][1]);
        }
    }
}

// ---------------------------------------------------------------------------
// Fused 2-layer MLP via mma.sync bf16-split emulation.
// out = relu(relu([x1|x2] @ W1 + b1) @ W2 + b2), W^T given as [128][K] hi/lo.
// ---------------------------------------------------------------------------
__global__ __launch_bounds__(256, 1)
void mlp_mma_kernel(const __nv_bfloat16* __restrict__ x1h, const __nv_bfloat16* __restrict__ x1l,
                    const __nv_bfloat16* __restrict__ x2h, const __nv_bfloat16* __restrict__ x2l,
                    int n,
                    const __nv_bfloat16* __restrict__ w1h, const __nv_bfloat16* __restrict__ w1l,
                    const float* __restrict__ b1,
                    const __nv_bfloat16* __restrict__ w2h, const __nv_bfloat16* __restrict__ w2l,
                    const float* __restrict__ b2,
                    float* __restrict__ out, int kchunks)
{
    char* sb = smem_raw;
    const int tid  = threadIdx.x;
    const int wid  = tid >> 5;
    const int lane = tid & 31;
    const int wm = wid >> 2;          // 0..1 : rows wm*64..+63
    const int wn = wid & 3;           // 0..3 : cols wn*32..+31
    const int g  = lane >> 2;
    const int tg = lane & 3;
    const int row0 = blockIdx.x * 128;
    const int K1 = kchunks * 128;

    float* b1s = (float*)(sb + SM_B1S);
    float* b2s = (float*)(sb + SM_B2S);
    if (tid < 128) { b1s[tid] = b1[tid]; b2s[tid] = b2[tid]; }

    float acc[4][4][4];
    #pragma unroll
    for (int mt = 0; mt < 4; ++mt)
        #pragma unroll
        for (int nt = 0; nt < 4; ++nt)
            #pragma unroll
            for (int r = 0; r < 4; ++r) acc[mt][nt][r] = 0.f;

    // ---------------- layer 1 ----------------
    for (int kc = 0; kc < kchunks; ++kc) {
        const __nv_bfloat16* xh = (kc == 0) ? x1h : x2h;
        const __nv_bfloat16* xl = (kc == 0) ? x1l : x2l;
        load_x(xh, xl, row0, n, sb, tid);
        load_w(w1h, w1l, K1, kc * 128, sb, tid);
        __syncthreads();
        compute_terms(acc, sb, wm, wn, lane);
        __syncthreads();
    }

    // ---- epilogue 1: bias+relu, bf16-split, write back into X smem ----
    {
        __nv_bfloat16* xh = (__nv_bfloat16*)(sb + SM_XHI);
        __nv_bfloat16* xl = (__nv_bfloat16*)(sb + SM_XLO);
        #pragma unroll
        for (int mt = 0; mt < 4; ++mt) {
            #pragma unroll
            for (int nt = 0; nt < 4; ++nt) {
                int col = wn * 32 + nt * 8 + tg * 2;
                float bc0 = b1s[col], bc1 = b1s[col + 1];
                #pragma unroll
                for (int h = 0; h < 2; ++h) {
                    int row = wm * 64 + mt * 16 + g + h * 8;
                    float v0 = fmaxf(acc[mt][nt][2 * h] + bc0, 0.f);
                    float v1 = fmaxf(acc[mt][nt][2 * h + 1] + bc1, 0.f);
                    uint32_t h2;
                    asm("cvt.rn.bf16x2.f32 %0, %1, %2;" : "=r"(h2) : "f"(v1), "f"(v0));
                    float r0 = __uint_as_float(h2 << 16);
                    float r1 = __uint_as_float(h2 & 0xffff0000u);
                    uint32_t l2;
                    float d0 = v0 - r0, d1 = v1 - r1;
                    asm("cvt.rn.bf16x2.f32 %0, %1, %2;" : "=r"(l2) : "f"(d1), "f"(d0));
                    *(uint32_t*)(xh + row * XSTRD + col) = h2;
                    *(uint32_t*)(xl + row * XSTRD + col) = l2;
                    acc[mt][nt][2 * h] = 0.f;
                    acc[mt][nt][2 * h + 1] = 0.f;
                }
            }
        }
    }
    // load W2 while epilogue writes settle (independent smem region)
    load_w(w2h, w2l, 128, 0, sb, tid);
    __syncthreads();

    // ---------------- layer 2 ----------------
    compute_terms(acc, sb, wm, wn, lane);
    __syncthreads();

    // ---- epilogue 2: bias+relu -> stage (aliases W smem) -> coalesced out ----
    float* stage = (float*)(sb + SM_WHI);   // [128][132] f32
    #pragma unroll
    for (int mt = 0; mt < 4; ++mt) {
        #pragma unroll
        for (int nt = 0; nt < 4; ++nt) {
            int col = wn * 32 + nt * 8 + tg * 2;
            float bc0 = b2s[col], bc1 = b2s[col + 1];
            #pragma unroll
            for (int h = 0; h < 2; ++h) {
                int row = wm * 64 + mt * 16 + g + h * 8;
                stage[row * 132 + col]     = fmaxf(acc[mt][nt][2 * h] + bc0, 0.f);
                stage[row * 132 + col + 1] = fmaxf(acc[mt][nt][2 * h + 1] + bc1, 0.f);
            }
        }
    }
    __syncthreads();
    #pragma unroll
    for (int f = tid; f < 4096; f += 256) {
        int row = f >> 5, c4 = f & 31;
        int gr = row0 + row;
        if (gr < n)
            *(float4*)(out + (size_t)gr * D + c4 * 4) = *(float4*)(stage + row * 132 + c4 * 4);
    }
}

// ---------------------------------------------------------------------------
// elementwise split: fp32 -> bf16 hi + bf16 lo
__global__ __launch_bounds__(256)
void split_kernel(const float* __restrict__ x, __nv_bfloat16* __restrict__ hi,
                  __nv_bfloat16* __restrict__ lo, long long n4)
{
    long long i = (long long)blockIdx.x * blockDim.x + threadIdx.x;
    if (i >= n4) return;
    float4 v = ((const float4*)x)[i];
    uint32_t* hp = (uint32_t*)hi;
    uint32_t* lp = (uint32_t*)lo;
    float vv[4] = {v.x, v.y, v.z, v.w};
    #pragma unroll
    for (int p = 0; p < 2; ++p) {
        float a = vv[2 * p], b = vv[2 * p + 1];
        uint32_t h2;
        asm("cvt.rn.bf16x2.f32 %0, %1, %2;" : "=r"(h2) : "f"(b), "f"(a));
        float ra = __uint_as_float(h2 << 16);
        float rb = __uint_as_float(h2 & 0xffff0000u);
        uint32_t l2;
        float da = a - ra, db = b - rb;
        asm("cvt.rn.bf16x2.f32 %0, %1, %2;" : "=r"(l2) : "f"(db), "f"(da));
        hp[i * 2 + p] = h2;
        lp[i * 2 + p] = l2;
    }
}

// transpose+split: W [K][128] fp32 -> W^T hi/lo [128][K] bf16
__global__ __launch_bounds__(256)
void tsplit_kernel(const float* __restrict__ W, __nv_bfloat16* __restrict__ th,
                   __nv_bfloat16* __restrict__ tl, int K)
{
    int i = blockIdx.x * blockDim.x + threadIdx.x;
    if (i >= K * 128) return;
    int k = i >> 7, nn = i & 127;
    float v = W[i];
    __nv_bfloat16 h = __float2bfloat16(v);
    float rh = __bfloat162float(h);
    th[(size_t)nn * K + k] = h;
    tl[(size_t)nn * K + k] = __float2bfloat16(v - rh);
}

// one warp per edge: gather 512B + red.add 512B
__global__ __launch_bounds__(256)
void scatter_add_kernel(const float* __restrict__ z, const int* __restrict__ col,
                        const int* __restrict__ row, float* __restrict__ m, int nedges)
{
    long long idx = (long long)blockIdx.x * blockDim.x + threadIdx.x;
    int e = (int)(idx >> 5);
    int ch = (int)(idx & 31);
    if (e < nedges) {
        int c = __ldg(col + e);
        int r = __ldg(row + e);
        float4 v = ((const float4*)(z + (size_t)c * D))[ch];
        float* dst = m + (size_t)r * D + ch * 4;
        asm volatile("red.global.add.v4.f32 [%0], {%1, %2, %3, %4};"
                     :: "l"(__cvta_generic_to_global(dst)),
                        "f"(v.x), "f"(v.y), "f"(v.z), "f"(v.w) : "memory");
    }
}

// ---------------------------------------------------------------------------
extern "C" void kernel_launch(void* const* d_in, const int* in_sizes, int n_in,
                              void* d_out, int out_size)
{
    const float* hv    = (const float*)d_in[0];
    const float* hc    = (const float*)d_in[1];
    const int*   row_v = (const int*)d_in[2];
    const int*   col_v = (const int*)d_in[3];
    const int*   row_c = (const int*)d_in[4];
    const int*   col_c = (const int*)d_in[5];
    const float* mw1   = (const float*)d_in[6];
    const float* mb1   = (const float*)d_in[7];
    const float* mw2   = (const float*)d_in[8];
    const float* mb2   = (const float*)d_in[9];
    const float* uw1   = (const float*)d_in[10];
    const float* ub1   = (const float*)d_in[11];
    const float* uw2   = (const float*)d_in[12];
    const float* ub2   = (const float*)d_in[13];

    const int NV = in_sizes[0] / D;
    const int NC = in_sizes[1] / D;
    const int E  = in_sizes[2];

    float* scratch;
    cudaGetSymbolAddress((void**)&scratch, g_scratch);
    float* zv = scratch;                          // [2*NC, D]
    float* zc = zv + (size_t)2 * NC * D;          // [2*NV, D]
    float* mv = zc + (size_t)2 * NV * D;          // [NV, D]
    float* mc = mv + (size_t)NV * D;              // [NC, D]

    __nv_bfloat16* bb = (__nv_bfloat16*)(scratch + 192000000);
    __nv_bfloat16* hv_hi = bb;
    __nv_bfloat16* hv_lo = hv_hi + (size_t)NV * D;
    __nv_bfloat16* hc_hi = hv_lo + (size_t)NV * D;
    __nv_bfloat16* hc_lo = hc_hi + (size_t)NC * D;
    __nv_bfloat16* mv_hi = hc_lo + (size_t)NC * D;
    __nv_bfloat16* mv_lo = mv_hi + (size_t)NV * D;
    __nv_bfloat16* mc_hi = mv_lo + (size_t)NV * D;
    __nv_bfloat16* mc_lo = mc_hi + (size_t)NC * D;
    __nv_bfloat16* wreg  = mc_lo + (size_t)NC * D;
    __nv_bfloat16* mwt1_hi = wreg;                 // 4 x 16384
    __nv_bfloat16* mwt1_lo = mwt1_hi + 65536;
    __nv_bfloat16* mwt2_hi = mwt1_lo + 65536;
    __nv_bfloat16* mwt2_lo = mwt2_hi + 65536;
    __nv_bfloat16* uwt1_hi = mwt2_lo + 65536;      // 2 x 32768
    __nv_bfloat16* uwt1_lo = uwt1_hi + 65536;
    __nv_bfloat16* uwt2_hi = uwt1_lo + 65536;      // 2 x 16384
    __nv_bfloat16* uwt2_lo = uwt2_hi + 32768;

    float* hv_new = (float*)d_out;
    float* hc_new = hv_new + (size_t)NV * D;

    cudaFuncSetAttribute(mlp_mma_kernel,
                         cudaFuncAttributeMaxDynamicSharedMemorySize, SMEM_BYTES);

    cudaMemsetAsync(mv, 0, (size_t)(NV + NC) * D * sizeof(float), 0);

    dim3 blk(256);

    // split inputs
    {
        long long n4 = (long long)NV * D / 4;
        split_kernel<<<(unsigned)((n4 + 255) / 256), blk>>>(hv, hv_hi, hv_lo, n4);
        n4 = (long long)NC * D / 4;
        split_kernel<<<(unsigned)((n4 + 255) / 256), blk>>>(hc, hc_hi, hc_lo, n4);
    }
    // transpose+split weights
    {
        int g128 = (128 * 128 + 255) / 256, g256 = (256 * 128 + 255) / 256;
        for (int i = 0; i < 4; ++i) {
            tsplit_kernel<<<g128, blk>>>(mw1 + (size_t)i * D * D, mwt1_hi + (size_t)i * 16384,
                                         mwt1_lo + (size_t)i * 16384, 128);
            tsplit_kernel<<<g128, blk>>>(mw2 + (size_t)i * D * D, mwt2_hi + (size_t)i * 16384,
                                         mwt2_lo + (size_t)i * 16384, 128);
        }
        for (int i = 0; i < 2; ++i) {
            tsplit_kernel<<<g256, blk>>>(uw1 + (size_t)i * 2 * D * D, uwt1_hi + (size_t)i * 32768,
                                         uwt1_lo + (size_t)i * 32768, 256);
            tsplit_kernel<<<g128, blk>>>(uw2 + (size_t)i * D * D, uwt2_hi + (size_t)i * 16384,
                                         uwt2_lo + (size_t)i * 16384, 128);
        }
    }

    int gc = (NC + 127) / 128;
    int gv = (NV + 127) / 128;

    // message MLPs (tensor cores via mma.sync)
    mlp_mma_kernel<<<gc, blk, SMEM_BYTES>>>(hc_hi, hc_lo, nullptr, nullptr, NC,
        mwt1_hi, mwt1_lo, mb1, mwt2_hi, mwt2_lo, mb2, zv, 1);
    mlp_mma_kernel<<<gc, blk, SMEM_BYTES>>>(hc_hi, hc_lo, nullptr, nullptr, NC,
        mwt1_hi + 16384, mwt1_lo + 16384, mb1 + D, mwt2_hi + 16384, mwt2_lo + 16384, mb2 + D,
        zv + (size_t)NC * D, 1);
    mlp_mma_kernel<<<gv, blk, SMEM_BYTES>>>(hv_hi, hv_lo, nullptr, nullptr, NV,
        mwt1_hi + 2 * 16384, mwt1_lo + 2 * 16384, mb1 + 2 * D,
        mwt2_hi + 2 * 16384, mwt2_lo + 2 * 16384, mb2 + 2 * D, zc, 1);
    mlp_mma_kernel<<<gv, blk, SMEM_BYTES>>>(hv_hi, hv_lo, nullptr, nullptr, NV,
        mwt1_hi + 3 * 16384, mwt1_lo + 3 * 16384, mb1 + 3 * D,
        mwt2_hi + 3 * 16384, mwt2_lo + 3 * 16384, mb2 + 3 * D, zc + (size_t)NV * D, 1);

    // scatter-adds
    long long tscat = (long long)E * 32;
    int gs = (int)((tscat + 255) / 256);
    scatter_add_kernel<<<gs, blk>>>(zv, col_v, row_v, mv, E);
    scatter_add_kernel<<<gs, blk>>>(zc, col_c, row_c, mc, E);

    // split messages
    {
        long long n4 = (long long)NV * D / 4;
        split_kernel<<<(unsigned)((n4 + 255) / 256), blk>>>(mv, mv_hi, mv_lo, n4);
        n4 = (long long)NC * D / 4;
        split_kernel<<<(unsigned)((n4 + 255) / 256), blk>>>(mc, mc_hi, mc_lo, n4);
    }

    // update MLPs (K1 = 256 via 2 chunks)
    mlp_mma_kernel<<<gv, blk, SMEM_BYTES>>>(hv_hi, hv_lo, mv_hi, mv_lo, NV,
        uwt1_hi, uwt1_lo, ub1, uwt2_hi, uwt2_lo, ub2, hv_new, 2);
    mlp_mma_kernel<<<gc, blk, SMEM_BYTES>>>(hc_hi, hc_lo, mc_hi, mc_lo, NC,
        uwt1_hi + 32768, uwt1_lo + 32768, ub1 + D,
        uwt2_hi + 16384, uwt2_lo + 16384, ub2 + D, hc_new, 2);
}

// round 5
// speedup vs baseline: 1.9005x; 1.1151x over previous
#include <cuda_runtime.h>
#include <cuda_bf16.h>
#include <cstdint>

#define D 128

// fp32 scratch: zv [2*NC*D] | zc [2*NV*D] | mv [NV*D] | mc [NC*D] = 192M floats
// then bf16 weight region (split+transposed), 458752 bf16
__device__ float g_scratch[192500000];

struct MlpSet {
    const __nv_bfloat16 *w1h, *w1l, *w2h, *w2l;
    const float *b1, *b2;
    float* out;
};

// ---------------- helpers ----------------
__device__ __forceinline__ uint32_t smem_u32(const void* p) {
    uint32_t a;
    asm("{ .reg .u64 t; cvta.to.shared.u64 t, %1; cvt.u32.u64 %0, t; }"
        : "=r"(a) : "l"(p));
    return a;
}

__device__ __forceinline__ void mma16816(float c[4],
                                         const uint32_t a[4],
                                         uint32_t b0, uint32_t b1) {
    asm volatile(
        "mma.sync.aligned.m16n8k16.row.col.f32.bf16.bf16.f32 "
        "{%0,%1,%2,%3}, {%4,%5,%6,%7}, {%8,%9}, {%0,%1,%2,%3};"
        : "+f"(c[0]), "+f"(c[1]), "+f"(c[2]), "+f"(c[3])
        : "r"(a[0]), "r"(a[1]), "r"(a[2]), "r"(a[3]), "r"(b0), "r"(b1));
}

__device__ __forceinline__ void ldmx4(uint32_t* r, uint32_t addr) {
    asm volatile("ldmatrix.sync.aligned.m8n8.x4.shared.b16 {%0,%1,%2,%3}, [%4];"
                 : "=r"(r[0]), "=r"(r[1]), "=r"(r[2]), "=r"(r[3]) : "r"(addr));
}

// split (a,b) fp32 pair -> bf16x2 hi + bf16x2 lo (residual)
__device__ __forceinline__ void split2(float a, float b, uint32_t& h2, uint32_t& l2) {
    asm("cvt.rn.bf16x2.f32 %0, %1, %2;" : "=r"(h2) : "f"(b), "f"(a));
    float ra = __uint_as_float(h2 << 16);
    float rb = __uint_as_float(h2 & 0xffff0000u);
    float da = a - ra, db = b - rb;
    asm("cvt.rn.bf16x2.f32 %0, %1, %2;" : "=r"(l2) : "f"(db), "f"(da));
}

// smem layout (bytes), row stride 136 bf16 = 272B
#define XSTRD 136
#define SM_XHI 0
#define SM_XLO 34816
#define SM_PHI 69632
#define SM_PLO 104448
#define SM_QHI 139264
#define SM_QLO 174080
#define SMEM_BYTES 208896

extern __shared__ char smem_raw[];

// load 128xD fp32 tile, split on the fly into bf16 hi/lo smem tiles
__device__ __forceinline__ void load_x_f32(const float* __restrict__ g,
                                           int row0, int n, char* sb, int tid) {
    __nv_bfloat16* xh = (__nv_bfloat16*)(sb + SM_XHI);
    __nv_bfloat16* xl = (__nv_bfloat16*)(sb + SM_XLO);
    #pragma unroll
    for (int f = tid; f < 2048; f += 256) {
        int row = f >> 4, q = f & 15;
        int gr = row0 + row;
        float4 v0 = make_float4(0.f, 0.f, 0.f, 0.f);
        float4 v1 = make_float4(0.f, 0.f, 0.f, 0.f);
        if (gr < n) {
            v0 = *(const float4*)(g + (size_t)gr * D + q * 8);
            v1 = *(const float4*)(g + (size_t)gr * D + q * 8 + 4);
        }
        uint4 hh, ll;
        split2(v0.x, v0.y, hh.x, ll.x);
        split2(v0.z, v0.w, hh.y, ll.y);
        split2(v1.x, v1.y, hh.z, ll.z);
        split2(v1.z, v1.w, hh.w, ll.w);
        *(uint4*)(xh + row * XSTRD + q * 8) = hh;
        *(uint4*)(xl + row * XSTRD + q * 8) = ll;
    }
}

// load pre-split W^T [128][K] chunk cols [k0, k0+128) into smem hi/lo
__device__ __forceinline__ void load_w(const __nv_bfloat16* __restrict__ gh,
                                       const __nv_bfloat16* __restrict__ gl,
                                       int K, int k0, char* dh, char* dl, int tid) {
    __nv_bfloat16* wh = (__nv_bfloat16*)dh;
    __nv_bfloat16* wl = (__nv_bfloat16*)dl;
    #pragma unroll
    for (int f = tid; f < 2048; f += 256) {
        int row = f >> 4, q = f & 15;
        uint4 vh = *(const uint4*)(gh + (size_t)row * K + k0 + q * 8);
        uint4 vl = *(const uint4*)(gl + (size_t)row * K + k0 + q * 8);
        *(uint4*)(wh + row * XSTRD + q * 8) = vh;
        *(uint4*)(wl + row * XSTRD + q * 8) = vl;
    }
}

// fused 3-term accumulate over 128 k's: acc += Ah@Bh + Ah@Bl + Al@Bh
__device__ __forceinline__ void compute_fused(float acc[4][4][4],
                                              uint32_t ahi, uint32_t alo,
                                              uint32_t bhi, uint32_t blo,
                                              int wm, int wn, int lane) {
    const int g  = lane >> 2;
    const int tg = lane & 3;
    const uint32_t aoff = (uint32_t)((lane & 15) * XSTRD + (lane >> 4) * 8) * 2;

    #pragma unroll
    for (int ks = 0; ks < 8; ++ks) {
        const int k0 = ks * 16;
        uint32_t Ah[4][4], Al[4][4];
        #pragma unroll
        for (int mt = 0; mt < 4; ++mt) {
            uint32_t base = (uint32_t)((wm * 64 + mt * 16) * XSTRD + k0) * 2 + aoff;
            ldmx4(Ah[mt], ahi + base);
            ldmx4(Al[mt], alo + base);
        }
        uint32_t Bh[4][2], Bl[4][2];
        #pragma unroll
        for (int nt = 0; nt < 4; ++nt) {
            int nrow = wn * 32 + nt * 8 + g;
            uint32_t p = (uint32_t)(nrow * XSTRD + k0 + tg * 2) * 2;
            asm volatile("ld.shared.b32 %0, [%1];" : "=r"(Bh[nt][0]) : "r"(bhi + p));
            asm volatile("ld.shared.b32 %0, [%1];" : "=r"(Bh[nt][1]) : "r"(bhi + p + 16));
            asm volatile("ld.shared.b32 %0, [%1];" : "=r"(Bl[nt][0]) : "r"(blo + p));
            asm volatile("ld.shared.b32 %0, [%1];" : "=r"(Bl[nt][1]) : "r"(blo + p + 16));
        }
        #pragma unroll
        for (int mt = 0; mt < 4; ++mt)
            #pragma unroll
            for (int nt = 0; nt < 4; ++nt) {
                mma16816(acc[mt][nt], Ah[mt], Bh[nt][0], Bh[nt][1]);
                mma16816(acc[mt][nt], Ah[mt], Bl[nt][0], Bl[nt][1]);
                mma16816(acc[mt][nt], Al[mt], Bh[nt][0], Bh[nt][1]);
            }
    }
}

// ---------------------------------------------------------------------------
// Fused 2-layer MLP (1 or 2 weight sets sharing the X tile)
// ---------------------------------------------------------------------------
__global__ __launch_bounds__(256, 1)
void mlp_mma_kernel(const float* __restrict__ x1, const float* __restrict__ x2, int n,
                    MlpSet s0, MlpSet s1, int nsets, int kchunks)
{
    char* sb = smem_raw;
    const int tid  = threadIdx.x;
    const int wid  = tid >> 5;
    const int lane = tid & 31;
    const int wm = wid >> 2;
    const int wn = wid & 3;
    const int g  = lane >> 2;
    const int tg = lane & 3;
    const int row0 = blockIdx.x * 128;

    const uint32_t su = smem_u32(sb);

    load_x_f32(x1, row0, n, sb, tid);

    float acc[4][4][4];
    #pragma unroll
    for (int mt = 0; mt < 4; ++mt)
        #pragma unroll
        for (int nt = 0; nt < 4; ++nt)
            #pragma unroll
            for (int r = 0; r < 4; ++r) acc[mt][nt][r] = 0.f;

    for (int set = 0; set < nsets; ++set) {
        const MlpSet S = set ? s1 : s0;
        const int K1 = kchunks * 128;

        // ---- layer 1 ----
        for (int kc = 0; kc < kchunks; ++kc) {
            if (kc == 1) load_x_f32(x2, row0, n, sb, tid);
            load_w(S.w1h, S.w1l, K1, kc * 128, sb + SM_PHI, sb + SM_PLO, tid);
            __syncthreads();
            compute_fused(acc, su + SM_XHI, su + SM_XLO, su + SM_PHI, su + SM_PLO,
                          wm, wn, lane);
            __syncthreads();
        }

        // ---- epilogue 1: bias+relu, split, hidden -> P; load W2 -> Q ----
        {
            __nv_bfloat16* hh = (__nv_bfloat16*)(sb + SM_PHI);
            __nv_bfloat16* hl = (__nv_bfloat16*)(sb + SM_PLO);
            #pragma unroll
            for (int mt = 0; mt < 4; ++mt)
                #pragma unroll
                for (int nt = 0; nt < 4; ++nt) {
                    int col = wn * 32 + nt * 8 + tg * 2;
                    float bc0 = __ldg(S.b1 + col), bc1 = __ldg(S.b1 + col + 1);
                    #pragma unroll
                    for (int h = 0; h < 2; ++h) {
                        int row = wm * 64 + mt * 16 + g + h * 8;
                        float v0 = fmaxf(acc[mt][nt][2 * h] + bc0, 0.f);
                        float v1 = fmaxf(acc[mt][nt][2 * h + 1] + bc1, 0.f);
                        uint32_t h2, l2;
                        split2(v0, v1, h2, l2);
                        *(uint32_t*)(hh + row * XSTRD + col) = h2;
                        *(uint32_t*)(hl + row * XSTRD + col) = l2;
                        acc[mt][nt][2 * h] = 0.f;
                        acc[mt][nt][2 * h + 1] = 0.f;
                    }
                }
        }
        load_w(S.w2h, S.w2l, 128, 0, sb + SM_QHI, sb + SM_QLO, tid);
        __syncthreads();

        // ---- layer 2 ----
        compute_fused(acc, su + SM_PHI, su + SM_PLO, su + SM_QHI, su + SM_QLO,
                      wm, wn, lane);
        __syncthreads();

        // ---- epilogue 2: bias+relu -> stage (aliases Q) -> coalesced out ----
        float* stage = (float*)(sb + SM_QHI);
        #pragma unroll
        for (int mt = 0; mt < 4; ++mt)
            #pragma unroll
            for (int nt = 0; nt < 4; ++nt) {
                int col = wn * 32 + nt * 8 + tg * 2;
                float bc0 = __ldg(S.b2 + col), bc1 = __ldg(S.b2 + col + 1);
                #pragma unroll
                for (int h = 0; h < 2; ++h) {
                    int row = wm * 64 + mt * 16 + g + h * 8;
                    stage[row * 132 + col]     = fmaxf(acc[mt][nt][2 * h] + bc0, 0.f);
                    stage[row * 132 + col + 1] = fmaxf(acc[mt][nt][2 * h + 1] + bc1, 0.f);
                    acc[mt][nt][2 * h] = 0.f;
                    acc[mt][nt][2 * h + 1] = 0.f;
                }
            }
        __syncthreads();
        #pragma unroll
        for (int f = tid; f < 4096; f += 256) {
            int row = f >> 5, c4 = f & 31;
            int gr = row0 + row;
            if (gr < n)
                *(float4*)(S.out + (size_t)gr * D + c4 * 4) =
                    *(float4*)(stage + row * 132 + c4 * 4);
        }
        __syncthreads();
    }
}

// ---------------------------------------------------------------------------
// single weight-prep launch: transpose + bf16-split all 12 matrices
// ---------------------------------------------------------------------------
__global__ __launch_bounds__(256)
void wprep_kernel(const float* __restrict__ mw1, const float* __restrict__ mw2,
                  const float* __restrict__ uw1, const float* __restrict__ uw2,
                  __nv_bfloat16* t1h, __nv_bfloat16* t1l,
                  __nv_bfloat16* t2h, __nv_bfloat16* t2l,
                  __nv_bfloat16* u1h, __nv_bfloat16* u1l,
                  __nv_bfloat16* u2h, __nv_bfloat16* u2l)
{
    int i = blockIdx.x * blockDim.x + threadIdx.x;
    if (i >= 229376) return;
    float v;
    __nv_bfloat16 *dh, *dl;
    size_t di;
    if (i < 131072) {                        // mw1 / mw2: 4 mats [128][128] each
        const float* src = (i < 65536) ? mw1 : mw2;
        int local = i & 65535;
        v = src[local];
        int mat = local >> 14, e = local & 16383;
        int k = e >> 7, nn = e & 127;
        di = (size_t)mat * 16384 + nn * 128 + k;
        dh = (i < 65536) ? t1h : t2h;
        dl = (i < 65536) ? t1l : t2l;
    } else if (i < 196608) {                 // uw1: 2 mats [256][128]
        int local = i - 131072;
        v = uw1[local];
        int mat = local >> 15, e = local & 32767;
        int k = e >> 7, nn = e & 127;
        di = (size_t)mat * 32768 + nn * 256 + k;
        dh = u1h; dl = u1l;
    } else {                                 // uw2: 2 mats [128][128]
        int local = i - 196608;
        v = uw2[local];
        int mat = local >> 14, e = local & 16383;
        int k = e >> 7, nn = e & 127;
        di = (size_t)mat * 16384 + nn * 128 + k;
        dh = u2h; dl = u2l;
    }
    __nv_bfloat16 h = __float2bfloat16(v);
    dh[di] = h;
    dl[di] = __float2bfloat16(v - __bfloat162float(h));
}

// one warp per edge: gather 512B + red.add 512B
__global__ __launch_bounds__(256)
void scatter_add_kernel(const float* __restrict__ z, const int* __restrict__ col,
                        const int* __restrict__ row, float* __restrict__ m, int nedges)
{
    long long idx = (long long)blockIdx.x * blockDim.x + threadIdx.x;
    int e = (int)(idx >> 5);
    int ch = (int)(idx & 31);
    if (e < nedges) {
        int c = __ldg(col + e);
        int r = __ldg(row + e);
        float4 v = ((const float4*)(z + (size_t)c * D))[ch];
        float* dst = m + (size_t)r * D + ch * 4;
        asm volatile("red.global.add.v4.f32 [%0], {%1, %2, %3, %4};"
                     :: "l"(__cvta_generic_to_global(dst)),
                        "f"(v.x), "f"(v.y), "f"(v.z), "f"(v.w) : "memory");
    }
}

// ---------------------------------------------------------------------------
extern "C" void kernel_launch(void* const* d_in, const int* in_sizes, int n_in,
                              void* d_out, int out_size)
{
    const float* hv    = (const float*)d_in[0];
    const float* hc    = (const float*)d_in[1];
    const int*   row_v = (const int*)d_in[2];
    const int*   col_v = (const int*)d_in[3];
    const int*   row_c = (const int*)d_in[4];
    const int*   col_c = (const int*)d_in[5];
    const float* mw1   = (const float*)d_in[6];
    const float* mb1   = (const float*)d_in[7];
    const float* mw2   = (const float*)d_in[8];
    const float* mb2   = (const float*)d_in[9];
    const float* uw1   = (const float*)d_in[10];
    const float* ub1   = (const float*)d_in[11];
    const float* uw2   = (const float*)d_in[12];
    const float* ub2   = (const float*)d_in[13];

    const int NV = in_sizes[0] / D;
    const int NC = in_sizes[1] / D;
    const int E  = in_sizes[2];

    float* scratch;
    cudaGetSymbolAddress((void**)&scratch, g_scratch);
    float* zv = scratch;                          // [2*NC, D]
    float* zc = zv + (size_t)2 * NC * D;          // [2*NV, D]
    float* mv = zc + (size_t)2 * NV * D;          // [NV, D]
    float* mc = mv + (size_t)NV * D;              // [NC, D]

    __nv_bfloat16* wb = (__nv_bfloat16*)(scratch + 192000000);
    __nv_bfloat16* mwt1_hi = wb;
    __nv_bfloat16* mwt1_lo = mwt1_hi + 65536;
    __nv_bfloat16* mwt2_hi = mwt1_lo + 65536;
    __nv_bfloat16* mwt2_lo = mwt2_hi + 65536;
    __nv_bfloat16* uwt1_hi = mwt2_lo + 65536;
    __nv_bfloat16* uwt1_lo = uwt1_hi + 65536;
    __nv_bfloat16* uwt2_hi = uwt1_lo + 65536;
    __nv_bfloat16* uwt2_lo = uwt2_hi + 32768;

    float* hv_new = (float*)d_out;
    float* hc_new = hv_new + (size_t)NV * D;

    cudaFuncSetAttribute(mlp_mma_kernel,
                         cudaFuncAttributeMaxDynamicSharedMemorySize, SMEM_BYTES);

    cudaMemsetAsync(mv, 0, (size_t)(NV + NC) * D * sizeof(float), 0);

    dim3 blk(256);
    wprep_kernel<<<(229376 + 255) / 256, blk>>>(mw1, mw2, uw1, uw2,
        mwt1_hi, mwt1_lo, mwt2_hi, mwt2_lo, uwt1_hi, uwt1_lo, uwt2_hi, uwt2_lo);

    int gc = (NC + 127) / 128;
    int gv = (NV + 127) / 128;

    // message MLPs: pos+neg fused per node type (X tile loaded once)
    {
        MlpSet p{mwt1_hi, mwt1_lo, mwt2_hi, mwt2_lo, mb1, mb2, zv};
        MlpSet q{mwt1_hi + 16384, mwt1_lo + 16384, mwt2_hi + 16384, mwt2_lo + 16384,
                 mb1 + D, mb2 + D, zv + (size_t)NC * D};
        mlp_mma_kernel<<<gc, blk, SMEM_BYTES>>>(hc, nullptr, NC, p, q, 2, 1);
    }
    {
        MlpSet p{mwt1_hi + 2 * 16384, mwt1_lo + 2 * 16384, mwt2_hi + 2 * 16384,
                 mwt2_lo + 2 * 16384, mb1 + 2 * D, mb2 + 2 * D, zc};
        MlpSet q{mwt1_hi + 3 * 16384, mwt1_lo + 3 * 16384, mwt2_hi + 3 * 16384,
                 mwt2_lo + 3 * 16384, mb1 + 3 * D, mb2 + 3 * D, zc + (size_t)NV * D};
        mlp_mma_kernel<<<gv, blk, SMEM_BYTES>>>(hv, nullptr, NV, p, q, 2, 1);
    }

    // scatter-adds
    long long tscat = (long long)E * 32;
    int gs = (int)((tscat + 255) / 256);
    scatter_add_kernel<<<gs, blk>>>(zv, col_v, row_v, mv, E);
    scatter_add_kernel<<<gs, blk>>>(zc, col_c, row_c, mc, E);

    // update MLPs (K1=256 via 2 fp32 chunks, messages read as fp32 directly)
    {
        MlpSet p{uwt1_hi, uwt1_lo, uwt2_hi, uwt2_lo, ub1, ub2, hv_new};
        mlp_mma_kernel<<<gv, blk, SMEM_BYTES>>>(hv, mv, NV, p, p, 1, 2);
    }
    {
        MlpSet p{uwt1_hi + 32768, uwt1_lo + 32768, uwt2_hi + 16384, uwt2_lo + 16384,
                 ub1 + D, ub2 + D, hc_new};
        mlp_mma_kernel<<<gc, blk, SMEM_BYTES>>>(hc, mc, NC, p, p, 1, 2);
    }
}

// round 6
// speedup vs baseline: 1.9099x; 1.0049x over previous
#include <cuda_runtime.h>
#include <cuda_bf16.h>
#include <cstdint>

#define D 128

// fp32 scratch: zv [2*NC*D] | zc [2*NV*D] | mv [NV*D] | mc [NC*D] = 192M floats
// then bf16 weight region (split+transposed)
__device__ float g_scratch[192500000];

struct MlpSet {
    const __nv_bfloat16 *w1h, *w1l, *w2h, *w2l;
    const float *b1, *b2;
    float* out;
};

// ---------------- helpers ----------------
__device__ __forceinline__ uint32_t smem_u32(const void* p) {
    uint32_t a;
    asm("{ .reg .u64 t; cvta.to.shared.u64 t, %1; cvt.u32.u64 %0, t; }"
        : "=r"(a) : "l"(p));
    return a;
}

__device__ __forceinline__ void mma16816(float c[4],
                                         const uint32_t a[4],
                                         uint32_t b0, uint32_t b1) {
    asm volatile(
        "mma.sync.aligned.m16n8k16.row.col.f32.bf16.bf16.f32 "
        "{%0,%1,%2,%3}, {%4,%5,%6,%7}, {%8,%9}, {%0,%1,%2,%3};"
        : "+f"(c[0]), "+f"(c[1]), "+f"(c[2]), "+f"(c[3])
        : "r"(a[0]), "r"(a[1]), "r"(a[2]), "r"(a[3]), "r"(b0), "r"(b1));
}

__device__ __forceinline__ void ldmx4(uint32_t* r, uint32_t addr) {
    asm volatile("ldmatrix.sync.aligned.m8n8.x4.shared.b16 {%0,%1,%2,%3}, [%4];"
                 : "=r"(r[0]), "=r"(r[1]), "=r"(r[2]), "=r"(r[3]) : "r"(addr));
}

__device__ __forceinline__ void split2(float a, float b, uint32_t& h2, uint32_t& l2) {
    asm("cvt.rn.bf16x2.f32 %0, %1, %2;" : "=r"(h2) : "f"(b), "f"(a));
    float ra = __uint_as_float(h2 << 16);
    float rb = __uint_as_float(h2 & 0xffff0000u);
    float da = a - ra, db = b - rb;
    asm("cvt.rn.bf16x2.f32 %0, %1, %2;" : "=r"(l2) : "f"(db), "f"(da));
}

// smem layout (bytes), row stride 136 bf16 = 272B
#define XSTRD 136
#define SM_XHI 0
#define SM_XLO 34816
#define SM_PHI 69632
#define SM_PLO 104448
#define SM_QHI 139264
#define SM_QLO 174080
#define SMEM_BYTES 208896

extern __shared__ char smem_raw[];

// load 128xD fp32 tile, split on the fly into bf16 hi/lo smem tiles
__device__ __forceinline__ void load_x_f32(const float* __restrict__ g,
                                           int row0, int n, char* sb, int tid) {
    __nv_bfloat16* xh = (__nv_bfloat16*)(sb + SM_XHI);
    __nv_bfloat16* xl = (__nv_bfloat16*)(sb + SM_XLO);
    #pragma unroll
    for (int f = tid; f < 2048; f += 256) {
        int row = f >> 4, q = f & 15;
        int gr = row0 + row;
        float4 v0 = make_float4(0.f, 0.f, 0.f, 0.f);
        float4 v1 = make_float4(0.f, 0.f, 0.f, 0.f);
        if (gr < n) {
            v0 = *(const float4*)(g + (size_t)gr * D + q * 8);
            v1 = *(const float4*)(g + (size_t)gr * D + q * 8 + 4);
        }
        uint4 hh, ll;
        split2(v0.x, v0.y, hh.x, ll.x);
        split2(v0.z, v0.w, hh.y, ll.y);
        split2(v1.x, v1.y, hh.z, ll.z);
        split2(v1.z, v1.w, hh.w, ll.w);
        *(uint4*)(xh + row * XSTRD + q * 8) = hh;
        *(uint4*)(xl + row * XSTRD + q * 8) = ll;
    }
}

// load pre-split W^T [128][K] chunk cols [k0, k0+128) into smem hi/lo
__device__ __forceinline__ void load_w(const __nv_bfloat16* __restrict__ gh,
                                       const __nv_bfloat16* __restrict__ gl,
                                       int K, int k0, char* dh, char* dl, int tid) {
    __nv_bfloat16* wh = (__nv_bfloat16*)dh;
    __nv_bfloat16* wl = (__nv_bfloat16*)dl;
    #pragma unroll
    for (int f = tid; f < 2048; f += 256) {
        int row = f >> 4, q = f & 15;
        uint4 vh = *(const uint4*)(gh + (size_t)row * K + k0 + q * 8);
        uint4 vl = *(const uint4*)(gl + (size_t)row * K + k0 + q * 8);
        *(uint4*)(wh + row * XSTRD + q * 8) = vh;
        *(uint4*)(wl + row * XSTRD + q * 8) = vl;
    }
}

// fused 3-term accumulate over 128 k's: acc += Ah@Bh + Ah@Bl + Al@Bh
__device__ __forceinline__ void compute_fused(float acc[4][4][4],
                                              uint32_t ahi, uint32_t alo,
                                              uint32_t bhi, uint32_t blo,
                                              int wm, int wn, int lane) {
    const int g  = lane >> 2;
    const int tg = lane & 3;
    const uint32_t aoff = (uint32_t)((lane & 15) * XSTRD + (lane >> 4) * 8) * 2;

    #pragma unroll
    for (int ks = 0; ks < 8; ++ks) {
        const int k0 = ks * 16;
        uint32_t Ah[4][4], Al[4][4];
        #pragma unroll
        for (int mt = 0; mt < 4; ++mt) {
            uint32_t base = (uint32_t)((wm * 64 + mt * 16) * XSTRD + k0) * 2 + aoff;
            ldmx4(Ah[mt], ahi + base);
            ldmx4(Al[mt], alo + base);
        }
        uint32_t Bh[4][2], Bl[4][2];
        #pragma unroll
        for (int nt = 0; nt < 4; ++nt) {
            int nrow = wn * 32 + nt * 8 + g;
            uint32_t p = (uint32_t)(nrow * XSTRD + k0 + tg * 2) * 2;
            asm volatile("ld.shared.b32 %0, [%1];" : "=r"(Bh[nt][0]) : "r"(bhi + p));
            asm volatile("ld.shared.b32 %0, [%1];" : "=r"(Bh[nt][1]) : "r"(bhi + p + 16));
            asm volatile("ld.shared.b32 %0, [%1];" : "=r"(Bl[nt][0]) : "r"(blo + p));
            asm volatile("ld.shared.b32 %0, [%1];" : "=r"(Bl[nt][1]) : "r"(blo + p + 16));
        }
        #pragma unroll
        for (int mt = 0; mt < 4; ++mt)
            #pragma unroll
            for (int nt = 0; nt < 4; ++nt) {
                mma16816(acc[mt][nt], Ah[mt], Bh[nt][0], Bh[nt][1]);
                mma16816(acc[mt][nt], Ah[mt], Bl[nt][0], Bl[nt][1]);
                mma16816(acc[mt][nt], Al[mt], Bh[nt][0], Bh[nt][1]);
            }
    }
}

// ---------------------------------------------------------------------------
// Fused 2-layer MLP (1 or 2 weight sets sharing the X tile)
// ---------------------------------------------------------------------------
__global__ __launch_bounds__(256, 1)
void mlp_mma_kernel(const float* __restrict__ x1, const float* __restrict__ x2, int n,
                    MlpSet s0, MlpSet s1, int nsets, int kchunks)
{
    char* sb = smem_raw;
    const int tid  = threadIdx.x;
    const int wid  = tid >> 5;
    const int lane = tid & 31;
    const int wm = wid >> 2;
    const int wn = wid & 3;
    const int g  = lane >> 2;
    const int tg = lane & 3;
    const int row0 = blockIdx.x * 128;

    const uint32_t su = smem_u32(sb);

    load_x_f32(x1, row0, n, sb, tid);

    float acc[4][4][4];
    #pragma unroll
    for (int mt = 0; mt < 4; ++mt)
        #pragma unroll
        for (int nt = 0; nt < 4; ++nt)
            #pragma unroll
            for (int r = 0; r < 4; ++r) acc[mt][nt][r] = 0.f;

    for (int set = 0; set < nsets; ++set) {
        const MlpSet S = set ? s1 : s0;
        const int K1 = kchunks * 128;

        // ---- layer 1 ----
        for (int kc = 0; kc < kchunks; ++kc) {
            if (kc == 1) load_x_f32(x2, row0, n, sb, tid);
            load_w(S.w1h, S.w1l, K1, kc * 128, sb + SM_PHI, sb + SM_PLO, tid);
            __syncthreads();
            compute_fused(acc, su + SM_XHI, su + SM_XLO, su + SM_PHI, su + SM_PLO,
                          wm, wn, lane);
            __syncthreads();
        }

        // ---- epilogue 1: bias+relu, split, hidden -> P; load W2 -> Q ----
        {
            __nv_bfloat16* hh = (__nv_bfloat16*)(sb + SM_PHI);
            __nv_bfloat16* hl = (__nv_bfloat16*)(sb + SM_PLO);
            #pragma unroll
            for (int mt = 0; mt < 4; ++mt)
                #pragma unroll
                for (int nt = 0; nt < 4; ++nt) {
                    int col = wn * 32 + nt * 8 + tg * 2;
                    float bc0 = __ldg(S.b1 + col), bc1 = __ldg(S.b1 + col + 1);
                    #pragma unroll
                    for (int h = 0; h < 2; ++h) {
                        int row = wm * 64 + mt * 16 + g + h * 8;
                        float v0 = fmaxf(acc[mt][nt][2 * h] + bc0, 0.f);
                        float v1 = fmaxf(acc[mt][nt][2 * h + 1] + bc1, 0.f);
                        uint32_t h2, l2;
                        split2(v0, v1, h2, l2);
                        *(uint32_t*)(hh + row * XSTRD + col) = h2;
                        *(uint32_t*)(hl + row * XSTRD + col) = l2;
                        acc[mt][nt][2 * h] = 0.f;
                        acc[mt][nt][2 * h + 1] = 0.f;
                    }
                }
        }
        load_w(S.w2h, S.w2l, 128, 0, sb + SM_QHI, sb + SM_QLO, tid);
        __syncthreads();

        // ---- layer 2 ----
        compute_fused(acc, su + SM_PHI, su + SM_PLO, su + SM_QHI, su + SM_QLO,
                      wm, wn, lane);
        __syncthreads();

        // ---- epilogue 2: bias+relu -> stage (aliases Q) -> coalesced out ----
        float* stage = (float*)(sb + SM_QHI);
        #pragma unroll
        for (int mt = 0; mt < 4; ++mt)
            #pragma unroll
            for (int nt = 0; nt < 4; ++nt) {
                int col = wn * 32 + nt * 8 + tg * 2;
                float bc0 = __ldg(S.b2 + col), bc1 = __ldg(S.b2 + col + 1);
                #pragma unroll
                for (int h = 0; h < 2; ++h) {
                    int row = wm * 64 + mt * 16 + g + h * 8;
                    stage[row * 132 + col]     = fmaxf(acc[mt][nt][2 * h] + bc0, 0.f);
                    stage[row * 132 + col + 1] = fmaxf(acc[mt][nt][2 * h + 1] + bc1, 0.f);
                    acc[mt][nt][2 * h] = 0.f;
                    acc[mt][nt][2 * h + 1] = 0.f;
                }
            }
        __syncthreads();
        #pragma unroll
        for (int f = tid; f < 4096; f += 256) {
            int row = f >> 5, c4 = f & 31;
            int gr = row0 + row;
            if (gr < n)
                *(float4*)(S.out + (size_t)gr * D + c4 * 4) =
                    *(float4*)(stage + row * 132 + c4 * 4);
        }
        __syncthreads();
    }
}

// ---------------------------------------------------------------------------
// single weight-prep launch: transpose + bf16-split all 12 matrices
// ---------------------------------------------------------------------------
__global__ __launch_bounds__(256)
void wprep_kernel(const float* __restrict__ mw1, const float* __restrict__ mw2,
                  const float* __restrict__ uw1, const float* __restrict__ uw2,
                  __nv_bfloat16* t1h, __nv_bfloat16* t1l,
                  __nv_bfloat16* t2h, __nv_bfloat16* t2l,
                  __nv_bfloat16* u1h, __nv_bfloat16* u1l,
                  __nv_bfloat16* u2h, __nv_bfloat16* u2l)
{
    int i = blockIdx.x * blockDim.x + threadIdx.x;
    if (i >= 229376) return;
    float v;
    __nv_bfloat16 *dh, *dl;
    size_t di;
    if (i < 131072) {
        const float* src = (i < 65536) ? mw1 : mw2;
        int local = i & 65535;
        v = src[local];
        int mat = local >> 14, e = local & 16383;
        int k = e >> 7, nn = e & 127;
        di = (size_t)mat * 16384 + nn * 128 + k;
        dh = (i < 65536) ? t1h : t2h;
        dl = (i < 65536) ? t1l : t2l;
    } else if (i < 196608) {
        int local = i - 131072;
        v = uw1[local];
        int mat = local >> 15, e = local & 32767;
        int k = e >> 7, nn = e & 127;
        di = (size_t)mat * 32768 + nn * 256 + k;
        dh = u1h; dl = u1l;
    } else {
        int local = i - 196608;
        v = uw2[local];
        int mat = local >> 14, e = local & 16383;
        int k = e >> 7, nn = e & 127;
        di = (size_t)mat * 16384 + nn * 128 + k;
        dh = u2h; dl = u2l;
    }
    __nv_bfloat16 h = __float2bfloat16(v);
    dh[di] = h;
    dl[di] = __float2bfloat16(v - __bfloat162float(h));
}

// one warp per edge: gather 512B + red.add 512B
__global__ __launch_bounds__(256)
void scatter_add_kernel(const float* __restrict__ z, const int* __restrict__ col,
                        const int* __restrict__ row, float* __restrict__ m, int nedges)
{
    long long idx = (long long)blockIdx.x * blockDim.x + threadIdx.x;
    int e = (int)(idx >> 5);
    int ch = (int)(idx & 31);
    if (e < nedges) {
        int c = __ldg(col + e);
        int r = __ldg(row + e);
        float4 v = ((const float4*)(z + (size_t)c * D))[ch];
        float* dst = m + (size_t)r * D + ch * 4;
        asm volatile("red.global.add.v4.f32 [%0], {%1, %2, %3, %4};"
                     :: "l"(__cvta_generic_to_global(dst)),
                        "f"(v.x), "f"(v.y), "f"(v.z), "f"(v.w) : "memory");
    }
}

// ---------------------------------------------------------------------------
extern "C" void kernel_launch(void* const* d_in, const int* in_sizes, int n_in,
                              void* d_out, int out_size)
{
    const float* hv    = (const float*)d_in[0];
    const float* hc    = (const float*)d_in[1];
    const int*   row_v = (const int*)d_in[2];
    const int*   col_v = (const int*)d_in[3];
    const int*   row_c = (const int*)d_in[4];
    const int*   col_c = (const int*)d_in[5];
    const float* mw1   = (const float*)d_in[6];
    const float* mb1   = (const float*)d_in[7];
    const float* mw2   = (const float*)d_in[8];
    const float* mb2   = (const float*)d_in[9];
    const float* uw1   = (const float*)d_in[10];
    const float* ub1   = (const float*)d_in[11];
    const float* uw2   = (const float*)d_in[12];
    const float* ub2   = (const float*)d_in[13];

    const int NV = in_sizes[0] / D;
    const int NC = in_sizes[1] / D;
    const int E  = in_sizes[2];

    float* scratch;
    cudaGetSymbolAddress((void**)&scratch, g_scratch);
    float* zv = scratch;                          // [2*NC, D]
    float* zc = zv + (size_t)2 * NC * D;          // [2*NV, D]
    float* mv = zc + (size_t)2 * NV * D;          // [NV, D]
    float* mc = mv + (size_t)NV * D;              // [NC, D]

    __nv_bfloat16* wb = (__nv_bfloat16*)(scratch + 192000000);
    __nv_bfloat16* mwt1_hi = wb;
    __nv_bfloat16* mwt1_lo = mwt1_hi + 65536;
    __nv_bfloat16* mwt2_hi = mwt1_lo + 65536;
    __nv_bfloat16* mwt2_lo = mwt2_hi + 65536;
    __nv_bfloat16* uwt1_hi = mwt2_lo + 65536;
    __nv_bfloat16* uwt1_lo = uwt1_hi + 65536;
    __nv_bfloat16* uwt2_hi = uwt1_lo + 65536;
    __nv_bfloat16* uwt2_lo = uwt2_hi + 32768;

    float* hv_new = (float*)d_out;
    float* hc_new = hv_new + (size_t)NV * D;

    // lazily created side stream + events (host-side resources only; reused)
    static cudaStream_t sB = nullptr;
    static cudaEvent_t evStart = nullptr, evZc = nullptr, evZv = nullptr,
                       evMc = nullptr, evMv = nullptr;
    if (sB == nullptr) {
        cudaStreamCreateWithFlags(&sB, cudaStreamNonBlocking);
        cudaEventCreateWithFlags(&evStart, cudaEventDisableTiming);
        cudaEventCreateWithFlags(&evZc, cudaEventDisableTiming);
        cudaEventCreateWithFlags(&evZv, cudaEventDisableTiming);
        cudaEventCreateWithFlags(&evMc, cudaEventDisableTiming);
        cudaEventCreateWithFlags(&evMv, cudaEventDisableTiming);
    }

    cudaFuncSetAttribute(mlp_mma_kernel,
                         cudaFuncAttributeMaxDynamicSharedMemorySize, SMEM_BYTES);

    dim3 blk(256);
    int gc = (NC + 127) / 128;
    int gv = (NV + 127) / 128;
    long long tscat = (long long)E * 32;
    int gs = (int)((tscat + 255) / 256);

    // ---- fork side stream; memset accumulators there (overlaps wprep/msgV) ----
    cudaEventRecord(evStart, 0);
    cudaStreamWaitEvent(sB, evStart, 0);
    cudaMemsetAsync(mv, 0, (size_t)(NV + NC) * D * sizeof(float), sB);

    // ---- main stream: weight prep, then msgV MLP (hv -> zc) ----
    wprep_kernel<<<(229376 + 255) / 256, blk>>>(mw1, mw2, uw1, uw2,
        mwt1_hi, mwt1_lo, mwt2_hi, mwt2_lo, uwt1_hi, uwt1_lo, uwt2_hi, uwt2_lo);

    {
        MlpSet p{mwt1_hi + 2 * 16384, mwt1_lo + 2 * 16384, mwt2_hi + 2 * 16384,
                 mwt2_lo + 2 * 16384, mb1 + 2 * D, mb2 + 2 * D, zc};
        MlpSet q{mwt1_hi + 3 * 16384, mwt1_lo + 3 * 16384, mwt2_hi + 3 * 16384,
                 mwt2_lo + 3 * 16384, mb1 + 3 * D, mb2 + 3 * D, zc + (size_t)NV * D};
        mlp_mma_kernel<<<gv, blk, SMEM_BYTES>>>(hv, nullptr, NV, p, q, 2, 1);
    }
    cudaEventRecord(evZc, 0);

    // ---- side stream: scatter_c (zc -> mc), hidden under msgC MLP ----
    cudaStreamWaitEvent(sB, evZc, 0);
    scatter_add_kernel<<<gs, blk, 0, sB>>>(zc, col_c, row_c, mc, E);
    cudaEventRecord(evMc, sB);

    // ---- main stream: msgC MLP (hc -> zv) ----
    {
        MlpSet p{mwt1_hi, mwt1_lo, mwt2_hi, mwt2_lo, mb1, mb2, zv};
        MlpSet q{mwt1_hi + 16384, mwt1_lo + 16384, mwt2_hi + 16384, mwt2_lo + 16384,
                 mb1 + D, mb2 + D, zv + (size_t)NC * D};
        mlp_mma_kernel<<<gc, blk, SMEM_BYTES>>>(hc, nullptr, NC, p, q, 2, 1);
    }
    cudaEventRecord(evZv, 0);

    // ---- side stream: scatter_v (zv -> mv), hidden under update-c MLP ----
    cudaStreamWaitEvent(sB, evZv, 0);
    scatter_add_kernel<<<gs, blk, 0, sB>>>(zv, col_v, row_v, mv, E);
    cudaEventRecord(evMv, sB);

    // ---- main stream: update-c MLP (hc, mc -> hc_new) ----
    cudaStreamWaitEvent(0, evMc, 0);
    {
        MlpSet p{uwt1_hi + 32768, uwt1_lo + 32768, uwt2_hi + 16384, uwt2_lo + 16384,
                 ub1 + D, ub2 + D, hc_new};
        mlp_mma_kernel<<<gc, blk, SMEM_BYTES>>>(hc, mc, NC, p, p, 1, 2);
    }

    // ---- main stream: update-v MLP (hv, mv -> hv_new); joins side stream ----
    cudaStreamWaitEvent(0, evMv, 0);
    {
        MlpSet p{uwt1_hi, uwt1_lo, uwt2_hi, uwt2_lo, ub1, ub2, hv_new};
        mlp_mma_kernel<<<gv, blk, SMEM_BYTES>>>(hv, mv, NV, p, p, 1, 2);
    }
}

// round 7
// speedup vs baseline: 1.9957x; 1.0449x over previous
#include <cuda_runtime.h>
#include <cuda_bf16.h>
#include <cstdint>

#define D 128

// fp32 scratch: zv [2*NC*D] | zc [2*NV*D] | mv [NV*D] | mc [NC*D] = 192M floats
// then bf16 weight region (split+transposed)
__device__ float g_scratch[192500000];

struct MlpSet {
    const __nv_bfloat16 *w1h, *w1l, *w2h, *w2l;
    const float *b1, *b2;
    float* out;
};

// ---------------- helpers ----------------
__device__ __forceinline__ uint32_t smem_u32(const void* p) {
    uint32_t a;
    asm("{ .reg .u64 t; cvta.to.shared.u64 t, %1; cvt.u32.u64 %0, t; }"
        : "=r"(a) : "l"(p));
    return a;
}

__device__ __forceinline__ void mma16816(float c[4],
                                         const uint32_t a[4],
                                         uint32_t b0, uint32_t b1) {
    asm volatile(
        "mma.sync.aligned.m16n8k16.row.col.f32.bf16.bf16.f32 "
        "{%0,%1,%2,%3}, {%4,%5,%6,%7}, {%8,%9}, {%0,%1,%2,%3};"
        : "+f"(c[0]), "+f"(c[1]), "+f"(c[2]), "+f"(c[3])
        : "r"(a[0]), "r"(a[1]), "r"(a[2]), "r"(a[3]), "r"(b0), "r"(b1));
}

__device__ __forceinline__ void ldmx4(uint32_t* r, uint32_t addr) {
    asm volatile("ldmatrix.sync.aligned.m8n8.x4.shared.b16 {%0,%1,%2,%3}, [%4];"
                 : "=r"(r[0]), "=r"(r[1]), "=r"(r[2]), "=r"(r[3]) : "r"(addr));
}

__device__ __forceinline__ void split2(float a, float b, uint32_t& h2, uint32_t& l2) {
    asm("cvt.rn.bf16x2.f32 %0, %1, %2;" : "=r"(h2) : "f"(b), "f"(a));
    float ra = __uint_as_float(h2 << 16);
    float rb = __uint_as_float(h2 & 0xffff0000u);
    float da = a - ra, db = b - rb;
    asm("cvt.rn.bf16x2.f32 %0, %1, %2;" : "=r"(l2) : "f"(db), "f"(da));
}

#define CP_ASYNC16(dst, src) \
    asm volatile("cp.async.cg.shared.global [%0], [%1], 16;" :: "r"(dst), "l"(src))
#define CP_COMMIT() asm volatile("cp.async.commit_group;" ::: "memory")
#define CP_WAIT0()  asm volatile("cp.async.wait_group 0;" ::: "memory")

// smem: 3 buffers of 69632B each (hi tile at +0, lo tile at +34816)
#define XSTRD 136
#define BUFSZ 69632
#define LOOFF 34816
#define SMEM_BYTES 208896

extern __shared__ char smem_raw[];

// load 128xD fp32 tile, split on the fly into bf16 hi/lo smem tiles (sync stores)
__device__ __forceinline__ void load_x_f32(const float* __restrict__ g,
                                           int row0, int n, char* buf, int tid) {
    __nv_bfloat16* xh = (__nv_bfloat16*)buf;
    __nv_bfloat16* xl = (__nv_bfloat16*)(buf + LOOFF);
    #pragma unroll
    for (int f = tid; f < 2048; f += 256) {
        int row = f >> 4, q = f & 15;
        int gr = row0 + row;
        float4 v0 = make_float4(0.f, 0.f, 0.f, 0.f);
        float4 v1 = make_float4(0.f, 0.f, 0.f, 0.f);
        if (gr < n) {
            v0 = *(const float4*)(g + (size_t)gr * D + q * 8);
            v1 = *(const float4*)(g + (size_t)gr * D + q * 8 + 4);
        }
        uint4 hh, ll;
        split2(v0.x, v0.y, hh.x, ll.x);
        split2(v0.z, v0.w, hh.y, ll.y);
        split2(v1.x, v1.y, hh.z, ll.z);
        split2(v1.z, v1.w, hh.w, ll.w);
        *(uint4*)(xh + row * XSTRD + q * 8) = hh;
        *(uint4*)(xl + row * XSTRD + q * 8) = ll;
    }
}

// async-copy a pre-split W^T [128][K] chunk (cols k0..k0+127) into a buffer
__device__ __forceinline__ void cp_w(const __nv_bfloat16* __restrict__ gh,
                                     const __nv_bfloat16* __restrict__ gl,
                                     int K, int k0, uint32_t bufaddr, int tid) {
    #pragma unroll
    for (int f = tid; f < 2048; f += 256) {
        int row = f >> 4, q = f & 15;
        uint32_t doff = (uint32_t)(row * XSTRD + q * 8) * 2;
        CP_ASYNC16(bufaddr + doff,         gh + (size_t)row * K + k0 + q * 8);
        CP_ASYNC16(bufaddr + LOOFF + doff, gl + (size_t)row * K + k0 + q * 8);
    }
}

// fused 3-term accumulate over 128 k's: acc += Ah@Bh + Ah@Bl + Al@Bh
__device__ __forceinline__ void compute_fused(float acc[4][4][4],
                                              uint32_t abuf, uint32_t bbuf,
                                              int wm, int wn, int lane) {
    const uint32_t ahi = abuf, alo = abuf + LOOFF;
    const uint32_t bhi = bbuf, blo = bbuf + LOOFF;
    const int g  = lane >> 2;
    const int tg = lane & 3;
    const uint32_t aoff = (uint32_t)((lane & 15) * XSTRD + (lane >> 4) * 8) * 2;

    #pragma unroll
    for (int ks = 0; ks < 8; ++ks) {
        const int k0 = ks * 16;
        uint32_t Ah[4][4], Al[4][4];
        #pragma unroll
        for (int mt = 0; mt < 4; ++mt) {
            uint32_t base = (uint32_t)((wm * 64 + mt * 16) * XSTRD + k0) * 2 + aoff;
            ldmx4(Ah[mt], ahi + base);
            ldmx4(Al[mt], alo + base);
        }
        uint32_t Bh[4][2], Bl[4][2];
        #pragma unroll
        for (int nt = 0; nt < 4; ++nt) {
            int nrow = wn * 32 + nt * 8 + g;
            uint32_t p = (uint32_t)(nrow * XSTRD + k0 + tg * 2) * 2;
            asm volatile("ld.shared.b32 %0, [%1];" : "=r"(Bh[nt][0]) : "r"(bhi + p));
            asm volatile("ld.shared.b32 %0, [%1];" : "=r"(Bh[nt][1]) : "r"(bhi + p + 16));
            asm volatile("ld.shared.b32 %0, [%1];" : "=r"(Bl[nt][0]) : "r"(blo + p));
            asm volatile("ld.shared.b32 %0, [%1];" : "=r"(Bl[nt][1]) : "r"(blo + p + 16));
        }
        #pragma unroll
        for (int mt = 0; mt < 4; ++mt)
            #pragma unroll
            for (int nt = 0; nt < 4; ++nt) {
                mma16816(acc[mt][nt], Ah[mt], Bh[nt][0], Bh[nt][1]);
                mma16816(acc[mt][nt], Ah[mt], Bl[nt][0], Bl[nt][1]);
                mma16816(acc[mt][nt], Al[mt], Bh[nt][0], Bh[nt][1]);
            }
    }
}

// bias+relu, bf16-split, write hidden acts into buffer (ldmatrix layout); zero acc
__device__ __forceinline__ void epilogue_hidden(float acc[4][4][4], const float* b1,
                                                char* buf, int wm, int wn, int g, int tg) {
    __nv_bfloat16* hh = (__nv_bfloat16*)buf;
    __nv_bfloat16* hl = (__nv_bfloat16*)(buf + LOOFF);
    #pragma unroll
    for (int mt = 0; mt < 4; ++mt)
        #pragma unroll
        for (int nt = 0; nt < 4; ++nt) {
            int col = wn * 32 + nt * 8 + tg * 2;
            float bc0 = __ldg(b1 + col), bc1 = __ldg(b1 + col + 1);
            #pragma unroll
            for (int h = 0; h < 2; ++h) {
                int row = wm * 64 + mt * 16 + g + h * 8;
                float v0 = fmaxf(acc[mt][nt][2 * h] + bc0, 0.f);
                float v1 = fmaxf(acc[mt][nt][2 * h + 1] + bc1, 0.f);
                uint32_t h2, l2;
                split2(v0, v1, h2, l2);
                *(uint32_t*)(hh + row * XSTRD + col) = h2;
                *(uint32_t*)(hl + row * XSTRD + col) = l2;
                acc[mt][nt][2 * h] = 0.f;
                acc[mt][nt][2 * h + 1] = 0.f;
            }
        }
}

// bias+relu -> stage buffer -> coalesced global; zeroes acc. Includes syncs.
__device__ __forceinline__ void epilogue_out(float acc[4][4][4], const float* b2,
                                             char* stagebuf, float* out, int row0, int n,
                                             int tid, int wm, int wn, int g, int tg) {
    float* stage = (float*)stagebuf;   // [128][132]
    #pragma unroll
    for (int mt = 0; mt < 4; ++mt)
        #pragma unroll
        for (int nt = 0; nt < 4; ++nt) {
            int col = wn * 32 + nt * 8 + tg * 2;
            float bc0 = __ldg(b2 + col), bc1 = __ldg(b2 + col + 1);
            #pragma unroll
            for (int h = 0; h < 2; ++h) {
                int row = wm * 64 + mt * 16 + g + h * 8;
                stage[row * 132 + col]     = fmaxf(acc[mt][nt][2 * h] + bc0, 0.f);
                stage[row * 132 + col + 1] = fmaxf(acc[mt][nt][2 * h + 1] + bc1, 0.f);
                acc[mt][nt][2 * h] = 0.f;
                acc[mt][nt][2 * h + 1] = 0.f;
            }
        }
    __syncthreads();
    #pragma unroll
    for (int f = tid; f < 4096; f += 256) {
        int row = f >> 5, c4 = f & 31;
        int gr = row0 + row;
        if (gr < n)
            *(float4*)(out + (size_t)gr * D + c4 * 4) = *(float4*)(stage + row * 132 + c4 * 4);
    }
    __syncthreads();
}

// ---------------------------------------------------------------------------
// Fused 2-layer MLP with cp.async double-buffered weights.
//  nsets==2 (kchunks==1): two weight sets sharing one X tile (message MLPs)
//  nsets==1 (kchunks==2): concat input K=256 (update MLPs)
// ---------------------------------------------------------------------------
__global__ __launch_bounds__(256, 1)
void mlp_mma_kernel(const float* __restrict__ x1, const float* __restrict__ x2, int n,
                    MlpSet s0, MlpSet s1, int nsets, int kchunks)
{
    char* sb = smem_raw;
    const int tid  = threadIdx.x;
    const int wid  = tid >> 5;
    const int lane = tid & 31;
    const int wm = wid >> 2;
    const int wn = wid & 3;
    const int g  = lane >> 2;
    const int tg = lane & 3;
    const int row0 = blockIdx.x * 128;

    const uint32_t su = smem_u32(sb);
    char *pB0 = sb, *pB1 = sb + BUFSZ, *pB2 = sb + 2 * BUFSZ;
    const uint32_t B0 = su, B1 = su + BUFSZ, B2 = su + 2 * BUFSZ;

    float acc[4][4][4];
    #pragma unroll
    for (int mt = 0; mt < 4; ++mt)
        #pragma unroll
        for (int nt = 0; nt < 4; ++nt)
            #pragma unroll
            for (int r = 0; r < 4; ++r) acc[mt][nt][r] = 0.f;

    if (nsets == 2) {
        // prefetch W1(s0) under the X conversion
        cp_w(s0.w1h, s0.w1l, 128, 0, B1, tid); CP_COMMIT();
        load_x_f32(x1, row0, n, pB0, tid);
        #pragma unroll
        for (int set = 0; set < 2; ++set) {
            const MlpSet S = set ? s1 : s0;
            CP_WAIT0(); __syncthreads();            // W1(set) ready in B1
            cp_w(S.w2h, S.w2l, 128, 0, B2, tid); CP_COMMIT();
            compute_fused(acc, B0, B1, wm, wn, lane);   // layer 1
            __syncthreads();
            epilogue_hidden(acc, S.b1, pB1, wm, wn, g, tg);  // hidden -> B1
            CP_WAIT0(); __syncthreads();            // W2 ready in B2 (+hidden visible)
            compute_fused(acc, B1, B2, wm, wn, lane);   // layer 2
            __syncthreads();
            if (set == 0) { cp_w(s1.w1h, s1.w1l, 128, 0, B1, tid); CP_COMMIT(); }
            epilogue_out(acc, S.b2, pB2, S.out, row0, n, tid, wm, wn, g, tg);
        }
    } else {
        const MlpSet S = s0;
        cp_w(S.w1h, S.w1l, 256, 0, B1, tid); CP_COMMIT();
        load_x_f32(x1, row0, n, pB0, tid);
        CP_WAIT0(); __syncthreads();                // W1 chunk0 in B1
        cp_w(S.w1h, S.w1l, 256, 128, B2, tid); CP_COMMIT();
        compute_fused(acc, B0, B1, wm, wn, lane);       // layer 1 chunk 0
        __syncthreads();
        load_x_f32(x2, row0, n, pB0, tid);          // x2 -> B0 (x1 dead)
        CP_WAIT0(); __syncthreads();                // W1 chunk1 in B2
        cp_w(S.w2h, S.w2l, 128, 0, B1, tid); CP_COMMIT();
        compute_fused(acc, B0, B2, wm, wn, lane);       // layer 1 chunk 1
        __syncthreads();
        epilogue_hidden(acc, S.b1, pB0, wm, wn, g, tg);  // hidden -> B0 (x2 dead)
        CP_WAIT0(); __syncthreads();                // W2 in B1
        compute_fused(acc, B0, B1, wm, wn, lane);       // layer 2
        __syncthreads();
        epilogue_out(acc, S.b2, pB2, S.out, row0, n, tid, wm, wn, g, tg);
    }
}

// ---------------------------------------------------------------------------
// single weight-prep launch: transpose + bf16-split all 12 matrices
// ---------------------------------------------------------------------------
__global__ __launch_bounds__(256)
void wprep_kernel(const float* __restrict__ mw1, const float* __restrict__ mw2,
                  const float* __restrict__ uw1, const float* __restrict__ uw2,
                  __nv_bfloat16* t1h, __nv_bfloat16* t1l,
                  __nv_bfloat16* t2h, __nv_bfloat16* t2l,
                  __nv_bfloat16* u1h, __nv_bfloat16* u1l,
                  __nv_bfloat16* u2h, __nv_bfloat16* u2l)
{
    int i = blockIdx.x * blockDim.x + threadIdx.x;
    if (i >= 229376) return;
    float v;
    __nv_bfloat16 *dh, *dl;
    size_t di;
    if (i < 131072) {
        const float* src = (i < 65536) ? mw1 : mw2;
        int local = i & 65535;
        v = src[local];
        int mat = local >> 14, e = local & 16383;
        int k = e >> 7, nn = e & 127;
        di = (size_t)mat * 16384 + nn * 128 + k;
        dh = (i < 65536) ? t1h : t2h;
        dl = (i < 65536) ? t1l : t2l;
    } else if (i < 196608) {
        int local = i - 131072;
        v = uw1[local];
        int mat = local >> 15, e = local & 32767;
        int k = e >> 7, nn = e & 127;
        di = (size_t)mat * 32768 + nn * 256 + k;
        dh = u1h; dl = u1l;
    } else {
        int local = i - 196608;
        v = uw2[local];
        int mat = local >> 14, e = local & 16383;
        int k = e >> 7, nn = e & 127;
        di = (size_t)mat * 16384 + nn * 128 + k;
        dh = u2h; dl = u2l;
    }
    __nv_bfloat16 h = __float2bfloat16(v);
    dh[di] = h;
    dl[di] = __float2bfloat16(v - __bfloat162float(h));
}

// one warp per edge: gather 512B + red.add 512B
__global__ __launch_bounds__(256)
void scatter_add_kernel(const float* __restrict__ z, const int* __restrict__ col,
                        const int* __restrict__ row, float* __restrict__ m, int nedges)
{
    long long idx = (long long)blockIdx.x * blockDim.x + threadIdx.x;
    int e = (int)(idx >> 5);
    int ch = (int)(idx & 31);
    if (e < nedges) {
        int c = __ldg(col + e);
        int r = __ldg(row + e);
        float4 v = ((const float4*)(z + (size_t)c * D))[ch];
        float* dst = m + (size_t)r * D + ch * 4;
        asm volatile("red.global.add.v4.f32 [%0], {%1, %2, %3, %4};"
                     :: "l"(__cvta_generic_to_global(dst)),
                        "f"(v.x), "f"(v.y), "f"(v.z), "f"(v.w) : "memory");
    }
}

// ---------------------------------------------------------------------------
extern "C" void kernel_launch(void* const* d_in, const int* in_sizes, int n_in,
                              void* d_out, int out_size)
{
    const float* hv    = (const float*)d_in[0];
    const float* hc    = (const float*)d_in[1];
    const int*   row_v = (const int*)d_in[2];
    const int*   col_v = (const int*)d_in[3];
    const int*   row_c = (const int*)d_in[4];
    const int*   col_c = (const int*)d_in[5];
    const float* mw1   = (const float*)d_in[6];
    const float* mb1   = (const float*)d_in[7];
    const float* mw2   = (const float*)d_in[8];
    const float* mb2   = (const float*)d_in[9];
    const float* uw1   = (const float*)d_in[10];
    const float* ub1   = (const float*)d_in[11];
    const float* uw2   = (const float*)d_in[12];
    const float* ub2   = (const float*)d_in[13];

    const int NV = in_sizes[0] / D;
    const int NC = in_sizes[1] / D;
    const int E  = in_sizes[2];

    float* scratch;
    cudaGetSymbolAddress((void**)&scratch, g_scratch);
    float* zv = scratch;                          // [2*NC, D]
    float* zc = zv + (size_t)2 * NC * D;          // [2*NV, D]
    float* mv = zc + (size_t)2 * NV * D;          // [NV, D]
    float* mc = mv + (size_t)NV * D;              // [NC, D]

    __nv_bfloat16* wb = (__nv_bfloat16*)(scratch + 192000000);
    __nv_bfloat16* mwt1_hi = wb;
    __nv_bfloat16* mwt1_lo = mwt1_hi + 65536;
    __nv_bfloat16* mwt2_hi = mwt1_lo + 65536;
    __nv_bfloat16* mwt2_lo = mwt2_hi + 65536;
    __nv_bfloat16* uwt1_hi = mwt2_lo + 65536;
    __nv_bfloat16* uwt1_lo = uwt1_hi + 65536;
    __nv_bfloat16* uwt2_hi = uwt1_lo + 65536;
    __nv_bfloat16* uwt2_lo = uwt2_hi + 32768;

    float* hv_new = (float*)d_out;
    float* hc_new = hv_new + (size_t)NV * D;

    static cudaStream_t sB = nullptr;
    static cudaEvent_t evStart = nullptr, evZc = nullptr, evZv = nullptr,
                       evMc = nullptr, evMv = nullptr;
    if (sB == nullptr) {
        cudaStreamCreateWithFlags(&sB, cudaStreamNonBlocking);
        cudaEventCreateWithFlags(&evStart, cudaEventDisableTiming);
        cudaEventCreateWithFlags(&evZc, cudaEventDisableTiming);
        cudaEventCreateWithFlags(&evZv, cudaEventDisableTiming);
        cudaEventCreateWithFlags(&evMc, cudaEventDisableTiming);
        cudaEventCreateWithFlags(&evMv, cudaEventDisableTiming);
    }

    cudaFuncSetAttribute(mlp_mma_kernel,
                         cudaFuncAttributeMaxDynamicSharedMemorySize, SMEM_BYTES);

    dim3 blk(256);
    int gc = (NC + 127) / 128;
    int gv = (NV + 127) / 128;
    long long tscat = (long long)E * 32;
    int gs = (int)((tscat + 255) / 256);

    // ---- fork side stream; memset accumulators there ----
    cudaEventRecord(evStart, 0);
    cudaStreamWaitEvent(sB, evStart, 0);
    cudaMemsetAsync(mv, 0, (size_t)(NV + NC) * D * sizeof(float), sB);

    // ---- main: weight prep, msgV MLP (hv -> zc) ----
    wprep_kernel<<<(229376 + 255) / 256, blk>>>(mw1, mw2, uw1, uw2,
        mwt1_hi, mwt1_lo, mwt2_hi, mwt2_lo, uwt1_hi, uwt1_lo, uwt2_hi, uwt2_lo);

    {
        MlpSet p{mwt1_hi + 2 * 16384, mwt1_lo + 2 * 16384, mwt2_hi + 2 * 16384,
                 mwt2_lo + 2 * 16384, mb1 + 2 * D, mb2 + 2 * D, zc};
        MlpSet q{mwt1_hi + 3 * 16384, mwt1_lo + 3 * 16384, mwt2_hi + 3 * 16384,
                 mwt2_lo + 3 * 16384, mb1 + 3 * D, mb2 + 3 * D, zc + (size_t)NV * D};
        mlp_mma_kernel<<<gv, blk, SMEM_BYTES>>>(hv, nullptr, NV, p, q, 2, 1);
    }
    cudaEventRecord(evZc, 0);

    // ---- side: scatter_c (zc -> mc) under msgC MLP ----
    cudaStreamWaitEvent(sB, evZc, 0);
    scatter_add_kernel<<<gs, blk, 0, sB>>>(zc, col_c, row_c, mc, E);
    cudaEventRecord(evMc, sB);

    // ---- main: msgC MLP (hc -> zv) ----
    {
        MlpSet p{mwt1_hi, mwt1_lo, mwt2_hi, mwt2_lo, mb1, mb2, zv};
        MlpSet q{mwt1_hi + 16384, mwt1_lo + 16384, mwt2_hi + 16384, mwt2_lo + 16384,
                 mb1 + D, mb2 + D, zv + (size_t)NC * D};
        mlp_mma_kernel<<<gc, blk, SMEM_BYTES>>>(hc, nullptr, NC, p, q, 2, 1);
    }
    cudaEventRecord(evZv, 0);

    // ---- side: scatter_v (zv -> mv) under update-c MLP ----
    cudaStreamWaitEvent(sB, evZv, 0);
    scatter_add_kernel<<<gs, blk, 0, sB>>>(zv, col_v, row_v, mv, E);
    cudaEventRecord(evMv, sB);

    // ---- main: update-c MLP (hc, mc -> hc_new) ----
    cudaStreamWaitEvent(0, evMc, 0);
    {
        MlpSet p{uwt1_hi + 32768, uwt1_lo + 32768, uwt2_hi + 16384, uwt2_lo + 16384,
                 ub1 + D, ub2 + D, hc_new};
        mlp_mma_kernel<<<gc, blk, SMEM_BYTES>>>(hc, mc, NC, p, p, 1, 2);
    }

    // ---- main: update-v MLP (hv, mv -> hv_new) ----
    cudaStreamWaitEvent(0, evMv, 0);
    {
        MlpSet p{uwt1_hi, uwt1_lo, uwt2_hi, uwt2_lo, ub1, ub2, hv_new};
        mlp_mma_kernel<<<gv, blk, SMEM_BYTES>>>(hv, mv, NV, p, p, 1, 2);
    }
}